// round 12
// baseline (speedup 1.0000x reference)
#include <cuda_runtime.h>
#include <cstdint>

#define NPROB 512            // problems (B*S)
#define NCTA  1024           // 2 CTAs per problem (column split)
#define MDIM  128
#define NDIM  256
#define HC    128            // columns owned per CTA
#define EPSF  1e-6f
#define MUF   0.01f
#define KITER 30
#define LMAX  25
#define MASK_ALL 0x01FFFFFFu
#define TPB   128            // 4 warps
#define PINJ  11             // pinned row-groups per warp -> rows 0..43
#define PROWS (PINJ * 4)     // 44 pinned rows
#define DYNSMEM (PROWS * HC * 4)   // 22528 B

typedef unsigned long long u64;

// Persistent device state
__device__ float    g_Aw[(size_t)NCTA * MDIM * HC];  // normalized A halves (64MB)
__device__ unsigned g_count, g_sense;                 // setup grid barrier
__device__ unsigned g_and[KITER], g_cnt[KITER];       // per-iter mask barrier
__device__ unsigned g_rel;                            // release: (epoch<<8)|stepbyte
__device__ unsigned g_pcount[NPROB], g_psense[NPROB]; // pair barriers (sense-reversal)
__device__ float    g_sx[NPROB * 2 * 5 * HC];         // setup exchange slots
__device__ unsigned g_sfeas[NPROB * 2];               // setup col-feas flags
__device__ float    g_xch[(size_t)NCTA * HC];         // per-iter Ag partials

// ---- packed f32x2 helpers (per-element IEEE fp32) ----
__device__ __forceinline__ u64 pack2(float x, float y) {
    u64 r; asm("mov.b64 %0, {%1, %2};" : "=l"(r) : "f"(x), "f"(y)); return r;
}
__device__ __forceinline__ void unpack2(u64 v, float& x, float& y) {
    asm("mov.b64 {%0, %1}, %2;" : "=f"(x), "=f"(y) : "l"(v));
}
__device__ __forceinline__ u64 fma2(u64 a, u64 b, u64 c) {
    u64 d; asm("fma.rn.f32x2 %0, %1, %2, %3;" : "=l"(d) : "l"(a), "l"(b), "l"(c));
    return d;
}
__device__ __forceinline__ u64 mul2(u64 a, u64 b) {
    u64 d; asm("mul.rn.f32x2 %0, %1, %2;" : "=l"(d) : "l"(a), "l"(b));
    return d;
}

__device__ __forceinline__ float warp_allreduce_add(float v) {
#pragma unroll
    for (int o = 16; o; o >>= 1) v += __shfl_xor_sync(0xffffffffu, v, o);
    return v;
}

__device__ __forceinline__ float dot4(float4 a, float4 b) {
    return a.x * b.x + a.y * b.y + a.z * b.z + a.w * b.w;
}

// Grid barrier (setup only). All NCTA co-resident: 7 CTAs/SM * 148 = 1036 >= 1024.
#define GRID_BARRIER()                                                        \
    do {                                                                      \
        __syncthreads();                                                      \
        if (tid == 0) {                                                       \
            const unsigned target = sense ^ 1u;                               \
            __threadfence();                                                  \
            if (atomicAdd(&g_count, 1u) == NCTA - 1u) {                       \
                atomicExch(&g_count, 0u);                                     \
                __threadfence();                                              \
                atomicExch(&g_sense, target);                                 \
            } else {                                                          \
                while (*(volatile unsigned*)&g_sense != target)               \
                    __nanosleep(64);                                          \
            }                                                                 \
            sense = target;                                                   \
            __threadfence();                                                  \
        }                                                                     \
        __syncthreads();                                                      \
    } while (0)

// Pair barrier (2 CTAs of one problem), sense-reversal -> graph-replay-safe.
#define PAIR_BARRIER()                                                        \
    do {                                                                      \
        __syncthreads();                                                      \
        if (tid == 0) {                                                       \
            const unsigned tgt = psense ^ 1u;                                 \
            __threadfence();                                                  \
            if (atomicAdd(&g_pcount[q], 1u) == 1u) {                          \
                atomicExch(&g_pcount[q], 0u);                                 \
                __threadfence();                                              \
                atomicExch(&g_psense[q], tgt);                                \
            } else {                                                          \
                while (*(volatile unsigned*)&g_psense[q] != tgt)              \
                    __nanosleep(32);                                          \
            }                                                                 \
            psense = tgt;                                                     \
            __threadfence();                                                  \
        }                                                                     \
        __syncthreads();                                                      \
    } while (0)

__global__ void __launch_bounds__(TPB, 7)
persist_kernel(const float* __restrict__ xraw,
               const float* __restrict__ Ain,
               const float* __restrict__ bin,
               const float* __restrict__ lowin,
               float* __restrict__ out)
{
    extern __shared__ __align__(16) float sA[];   // PROWS x HC pinned rows

    const int p    = blockIdx.x;
    const int q    = p >> 1;          // problem
    const int r    = p & 1;           // column-half rank
    const int tid  = threadIdx.x;
    const int lane = tid & 31;
    const int w    = tid >> 5;        // 0..3
    const int off  = 4 * lane;        // local col offset for this lane

    __shared__ __align__(16) float s_x[HC];
    __shared__ __align__(16) float s_grad[HC];
    __shared__ __align__(16) float s_lo[HC];
    __shared__ __align__(16) float s_xr[HC];
    __shared__ __align__(16) float s_bw[MDIM];
    __shared__ __align__(16) float s_Ax[MDIM];
    __shared__ __align__(16) float s_Ag[MDIM];
    __shared__ __align__(16) float s_v[MDIM];     // also norm temp in setup
    __shared__ __align__(16) float s_gb[4 * HC];  // per-warp gbar partials
    __shared__ unsigned s_mask;
    __shared__ float    s_step;
    __shared__ int      s_feas;

    const float* Araw = Ain + (size_t)q * MDIM * NDIM + r * HC;
    float*       Aw   = g_Aw + (size_t)p * MDIM * HC;

    unsigned sense  = *(volatile unsigned*)&g_sense;
    unsigned psense = *(volatile unsigned*)&g_psense[q];

    if (p == 0) {
        if (tid < KITER) { g_and[tid] = MASK_ALL; g_cnt[tid] = 0u; }
        if (tid == 0)    g_rel = 0u;
    }

    if (tid < HC) {
        s_lo[tid] = lowin[q * NDIM + r * HC + tid];
        s_xr[tid] = xraw[q * NDIM + r * HC + tid];
    }
    if (tid == 0) s_feas = 1;
    __syncthreads();

    const float4 l4 = *(const float4*)(s_lo + off);
    const float stepl = __uint_as_float((unsigned)(127 - lane) << 23);

    float* s_red = s_gb;   // setup alias

    // ---- setup pass 1: raw partials (norm^2, row-sum, dot with lower) ------
    for (int j = 0; j < 32; j++) {
        const int m = w + 4 * j;
        const float4 a = *(const float4*)(Araw + (size_t)m * NDIM + off);
        float ss  = warp_allreduce_add(dot4(a, a));
        float rad = warp_allreduce_add(a.x + a.y + a.z + a.w);
        float rsd = warp_allreduce_add(dot4(a, l4));
        if (lane == 0) { s_bw[m] = ss; s_Ax[m] = rad; s_Ag[m] = rsd; }
    }
    __syncthreads();
    {
        const int base = (q * 2 + r) * 5 * HC;
        if (tid < HC) {
            g_sx[base + 0 * HC + tid] = s_bw[tid];
            g_sx[base + 1 * HC + tid] = s_Ax[tid];
            g_sx[base + 2 * HC + tid] = s_Ag[tid];
        }
    }
    PAIR_BARRIER();   // exchange #1

    if (tid < HC) {
        const int b0 = (q * 2 + 0) * 5 * HC;
        const int b1 = (q * 2 + 1) * 5 * HC;
        const float ss  = g_sx[b0 + 0 * HC + tid] + g_sx[b1 + 0 * HC + tid];
        const float rad = g_sx[b0 + 1 * HC + tid] + g_sx[b1 + 1 * HC + tid];
        const float rsd = g_sx[b0 + 2 * HC + tid] + g_sx[b1 + 2 * HC + tid];
        const float norm = fmaxf(sqrtf(ss), 1e-12f);
        s_v[tid] = norm;                              // stash norm
        const float bwm = bin[q * MDIM + tid] / norm;
        s_bw[tid] = bwm;
        const float ad = rad / norm;
        const float sd = rsd / norm;
        s_red[tid] = (ad > 0.f) ? (bwm - sd) / fmaxf(ad, 1e-12f)
                                : __int_as_float(0x7f800000);
    }
    __syncthreads();
    for (int o2 = 64; o2 >= 1; o2 >>= 1) {
        if (tid < o2) s_red[tid] = fminf(s_red[tid], s_red[tid + o2]);
        __syncthreads();
    }
    const float t = fmaxf(0.5f * s_red[0], 2.f * EPSF);
    __syncthreads();

    // ---- setup pass 2: normalize+store+pin, seed Ax partials on x0=lo+t ----
    {
        float4 xq4;
        xq4.x = l4.x + t; xq4.y = l4.y + t; xq4.z = l4.z + t; xq4.w = l4.w + t;
        for (int j = 0; j < 32; j++) {
            const int m = w + 4 * j;
            const float4 a = *(const float4*)(Araw + (size_t)m * NDIM + off);
            const float nm = s_v[m];
            float4 w0;
            w0.x = a.x / nm; w0.y = a.y / nm; w0.z = a.z / nm; w0.w = a.w / nm;
            *(float4*)(Aw + (size_t)m * HC + off) = w0;
            if (j < PINJ) *(float4*)(sA + m * HC + off) = w0;
            float d = warp_allreduce_add(dot4(w0, xq4));
            if (lane == 0) s_Ax[m] = d;   // partial
        }
        if (tid < HC) {
            const float x0 = s_lo[tid] + t;
            if (!(x0 >= s_lo[tid] + EPSF)) atomicAnd(&s_feas, 0);
        }
    }
    __syncthreads();
    {
        const int base = (q * 2 + r) * 5 * HC;
        if (tid < HC) g_sx[base + 3 * HC + tid] = s_Ax[tid];
        if (tid == 0) g_sfeas[q * 2 + r] = (unsigned)s_feas;
    }
    PAIR_BARRIER();   // exchange #2

    if (tid < HC) {
        const int b0 = (q * 2 + 0) * 5 * HC;
        const int b1 = (q * 2 + 1) * 5 * HC;
        const float axs = g_sx[b0 + 3 * HC + tid] + g_sx[b1 + 3 * HC + tid];
        s_Ax[tid] = axs;
        if (!(axs <= s_bw[tid] - EPSF)) atomicAnd(&s_feas, 0);
    }
    if (tid == 0) {
        if (!g_sfeas[q * 2 + (1 - r)]) atomicAnd(&s_feas, 0);
    }
    __syncthreads();
    if (tid < HC) {
        float xv = s_lo[tid] + t;
        if (!s_feas) xv = 0.5f * (fmaxf(xv, 0.f) + s_lo[tid]);
        s_x[tid] = xv;
    }
    __syncthreads();
    if (!s_feas) {   // rare repair: recompute Ax partials on repaired x
        const float4 rx = *(const float4*)(s_x + off);
        for (int j = 0; j < 32; j++) {
            const int m = w + 4 * j;
            const float* src = (j < PINJ) ? (sA + m * HC)
                                          : (Aw + (size_t)m * HC);
            const float4 a = *(const float4*)(src + off);
            float d = warp_allreduce_add(dot4(a, rx));
            if (lane == 0) s_Ag[m] = d;
        }
        __syncthreads();
        const int base = (q * 2 + r) * 5 * HC;
        if (tid < HC) g_sx[base + 4 * HC + tid] = s_Ag[tid];
        PAIR_BARRIER();   // exchange #3
        if (tid < HC) {
            const int b0 = (q * 2 + 0) * 5 * HC;
            const int b1 = (q * 2 + 1) * 5 * HC;
            s_Ax[tid] = g_sx[b0 + 4 * HC + tid] + g_sx[b1 + 4 * HC + tid];
        }
    }

    GRID_BARRIER();   // barrier-state init + everyone's setup done

    if (tid < HC)
        s_v[tid] = __fdividef(MUF, fmaxf(s_bw[tid] - s_Ax[tid], 1e-12f));
    if (tid == 0) s_mask = MASK_ALL;
    __syncthreads();

    // ---------------- main loop ---------------------------------------------
    for (int k = 0; k < KITER; k++) {
        // ---- pass G: gbar partials over ALL 128 rows (own 128 cols) --------
        u64 ga0 = 0ull, ga1 = 0ull;
#pragma unroll 7
        for (int j = PINJ; j < 32; j++) {
            const int m = w + 4 * j;
            const ulonglong2 a = *(const ulonglong2*)(Aw + (size_t)m * HC + off);
            const float v_ = s_v[m];
            const u64 vv = pack2(v_, v_);
            ga0 = fma2(a.x, vv, ga0);
            ga1 = fma2(a.y, vv, ga1);
        }
#pragma unroll
        for (int j = 0; j < PINJ; j++) {
            const int m = w + 4 * j;
            const ulonglong2 a = *(const ulonglong2*)(sA + m * HC + off);
            const float v_ = s_v[m];
            const u64 vv = pack2(v_, v_);
            ga0 = fma2(a.x, vv, ga0);
            ga1 = fma2(a.y, vv, ga1);
        }
        {
            ulonglong2 t0; t0.x = ga0; t0.y = ga1;
            *(ulonglong2*)(s_gb + w * HC + off) = t0;
        }
        __syncthreads();

        // ---- grad + column masks (own columns) ------------------------------
        if (tid < HC) {
            const float gb = s_gb[tid] + s_gb[HC + tid]
                           + s_gb[2 * HC + tid] + s_gb[3 * HC + tid];
            const float xv  = s_x[tid];
            const float lov = s_lo[tid];
            const float slo = fmaxf(xv - lov, 1e-12f);
            const float gr  = (xv - s_xr[tid]) + gb + __fdividef(MUF, slo);
            s_grad[tid] = gr;

            const float lim = lov + EPSF;
            if (!(gr <= 0.f && xv >= lim)) {
                unsigned mk = MASK_ALL;
                float st = 1.f;
#pragma unroll
                for (int l = 0; l < LMAX; l++) {
                    const float c = fmaf(-st, gr, xv);
                    if (!(c >= lim)) mk &= ~(1u << l);
                    st *= 0.5f;
                }
                if (mk != MASK_ALL) atomicAnd(&s_mask, mk);
            }
        }
        __syncthreads();

        // ---- pass A: Ag partial dots over ALL 128 rows ----------------------
        const ulonglong2 gq = *(const ulonglong2*)(s_grad + off);
#pragma unroll 7
        for (int j = PINJ; j < 32; j++) {
            const int m = w + 4 * j;
            const ulonglong2 a = *(const ulonglong2*)(Aw + (size_t)m * HC + off);
            u64 s = mul2(a.x, gq.x);
            s = fma2(a.y, gq.y, s);
            float sl, sh; unpack2(s, sl, sh);
            float ag = warp_allreduce_add(sl + sh);
            if (lane == 0) s_Ag[m] = ag;
        }
#pragma unroll
        for (int j = 0; j < PINJ; j++) {
            const int m = w + 4 * j;
            const ulonglong2 a = *(const ulonglong2*)(sA + m * HC + off);
            u64 s = mul2(a.x, gq.x);
            s = fma2(a.y, gq.y, s);
            float sl, sh; unpack2(s, sl, sh);
            float ag = warp_allreduce_add(sl + sh);
            if (lane == 0) s_Ag[m] = ag;
        }
        __syncthreads();
        if (tid < HC) g_xch[(size_t)(q * 2 + r) * HC + tid] = s_Ag[tid];

        PAIR_BARRIER();   // publish + collect Ag partials

        if (tid < HC)
            s_Ag[tid] = g_xch[(size_t)(q * 2) * HC + tid]
                      + g_xch[(size_t)(q * 2 + 1) * HC + tid];
        __syncthreads();

        // ---- row masks (this rank handles rows 64r .. 64r+63) ---------------
        {
            unsigned wmask = MASK_ALL;
            const int rbase = 64 * r + 16 * w;
#pragma unroll
            for (int jj = 0; jj < 16; jj++) {
                const int m = rbase + jj;
                const float ag  = s_Ag[m];
                const float axc = fmaf(-stepl, ag, s_Ax[m]);
                const unsigned bits =
                    __ballot_sync(0xffffffffu, axc <= s_bw[m] - EPSF);
                wmask &= (bits | ~MASK_ALL);
            }
            if (lane == 0 && wmask != MASK_ALL) atomicAnd(&s_mask, wmask);
        }
        __syncthreads();

        // ---- flat global barrier; release word carries the step -------------
        if (tid == 0) {
            atomicAnd(&g_and[k], s_mask);
            __threadfence();
            if (atomicAdd(&g_cnt[k], 1u) == NCTA - 1u) {
                __threadfence();
                const unsigned fin = *(volatile unsigned*)&g_and[k] & MASK_ALL;
                const unsigned sb = fin ? (unsigned)(__ffs(fin) - 1) : 0xFFu;
                atomicExch(&g_rel, ((unsigned)(k + 1) << 8) | sb);
            }
            unsigned relv;
            while (((relv = *(volatile unsigned*)&g_rel) >> 8) != (unsigned)(k + 1))
                __nanosleep(32);
            const unsigned sb = relv & 0xFFu;
            s_step = (sb == 0xFFu) ? 0.f
                                   : __uint_as_float((127u - sb) << 23);
            s_mask = MASK_ALL;
        }
        __syncthreads();

        // ---- updates: x (own cols), Ax + v (all 128 rows, replicated) -------
        if (tid < HC) {
            s_x[tid] = fmaf(-s_step, s_grad[tid], s_x[tid]);
            const float nAx = fmaf(-s_step, s_Ag[tid], s_Ax[tid]);
            s_Ax[tid] = nAx;
            s_v[tid]  = __fdividef(MUF, fmaxf(s_bw[tid] - nAx, 1e-12f));
        }
        __syncthreads();
    }

    // finalize: relu(x) -> own columns
    if (tid < HC) out[q * NDIM + r * HC + tid] = fmaxf(s_x[tid], 0.f);
}

extern "C" void kernel_launch(void* const* d_in, const int* in_sizes, int n_in,
                              void* d_out, int out_size) {
    // Identify inputs by size (dict order: x_raw, A, b, lower).
    int iA = 1, ib = 2, iv1 = 0, iv2 = 3;
    {
        int big = -1, small = -1, v1 = -1, v2 = -1;
        for (int i = 0; i < n_in; i++) {
            if (in_sizes[i] == NPROB * MDIM * NDIM) big = i;
            else if (in_sizes[i] == NPROB * MDIM)   small = i;
            else if (v1 < 0) v1 = i;
            else             v2 = i;
        }
        if (big >= 0 && small >= 0 && v1 >= 0 && v2 >= 0) {
            iA = big; ib = small; iv1 = v1; iv2 = v2;
        }
    }
    const float* xr  = (const float*)d_in[iv1];
    const float* A   = (const float*)d_in[iA];
    const float* b   = (const float*)d_in[ib];
    const float* low = (const float*)d_in[iv2];
    float* out = (float*)d_out;

    persist_kernel<<<NCTA, TPB, DYNSMEM>>>(xr, A, b, low, out);
}

// round 13
// speedup vs baseline: 1.2953x; 1.2953x over previous
#include <cuda_runtime.h>
#include <cstdint>

#define NPROB 512            // B*S = 32*16
#define MDIM  128
#define NDIM  256
#define EPSF  1e-6f
#define MUF   0.01f
#define KITER 30
#define LMAX  25
#define MASK_ALL 0x01FFFFFFu // 25 bits
#define TPB   256
#define CJ    5              // cached row-groups per warp (rows 0..39 in smem)
#define CROWS (CJ * 8)       // 40 rows cached
#define DYNSMEM (CROWS * NDIM * 4)

typedef unsigned long long u64;

// Persistent device state
__device__ float    g_Aw[(size_t)NPROB * MDIM * NDIM]; // row-normalized A (64MB)
__device__ unsigned g_count;                            // setup barrier counter
__device__ unsigned g_sense;                            // setup barrier sense
__device__ unsigned g_and[KITER];                       // per-iter AND of masks
__device__ unsigned g_cnt[KITER];                       // per-iter arrival count
__device__ unsigned g_rel;                              // release: (epoch<<8)|stepbyte

// ---- packed f32x2 helpers (sm_103a FFMA2 path; per-element IEEE fp32) ----
__device__ __forceinline__ u64 pack2(float x, float y) {
    u64 r; asm("mov.b64 %0, {%1, %2};" : "=l"(r) : "f"(x), "f"(y)); return r;
}
__device__ __forceinline__ void unpack2(u64 v, float& x, float& y) {
    asm("mov.b64 {%0, %1}, %2;" : "=f"(x), "=f"(y) : "l"(v));
}
__device__ __forceinline__ u64 fma2(u64 a, u64 b, u64 c) {
    u64 d; asm("fma.rn.f32x2 %0, %1, %2, %3;" : "=l"(d) : "l"(a), "l"(b), "l"(c));
    return d;
}
__device__ __forceinline__ u64 mul2(u64 a, u64 b) {
    u64 d; asm("mul.rn.f32x2 %0, %1, %2;" : "=l"(d) : "l"(a), "l"(b));
    return d;
}

// NOTE: redux.sync.add.f32 is NOT supported on sm_103 (ptxas rejects it).
__device__ __forceinline__ float warp_allreduce_add(float v) {
#pragma unroll
    for (int o = 16; o; o >>= 1) v += __shfl_xor_sync(0xffffffffu, v, o);
    return v;
}

__device__ __forceinline__ float dot8(float4 a0, float4 a1, float4 b0, float4 b1) {
    float s = a0.x * b0.x + a0.y * b0.y + a0.z * b0.z + a0.w * b0.w;
    s += a1.x * b1.x + a1.y * b1.y + a1.z * b1.z + a1.w * b1.w;
    return s;
}

// Setup-only grid barrier (runs once). All NPROB CTAs co-resident:
// __launch_bounds__(256,4) + ~55KB smem/CTA -> 4 CTAs/SM * 148 = 592 >= 512.
#define GRID_BARRIER()                                                        \
    do {                                                                      \
        __syncthreads();                                                      \
        if (tid == 0) {                                                       \
            const unsigned target = sense ^ 1u;                               \
            __threadfence();                                                  \
            if (atomicAdd(&g_count, 1u) == NPROB - 1u) {                      \
                atomicExch(&g_count, 0u);                                     \
                __threadfence();                                              \
                atomicExch(&g_sense, target);                                 \
            } else {                                                          \
                while (*(volatile unsigned*)&g_sense != target)               \
                    __nanosleep(64);                                          \
            }                                                                 \
            sense = target;                                                   \
            __threadfence();                                                  \
        }                                                                     \
        __syncthreads();                                                      \
    } while (0)

__global__ void __launch_bounds__(TPB, 4)
persist_kernel(const float* __restrict__ xraw,
               const float* __restrict__ Ain,
               const float* __restrict__ bin,
               const float* __restrict__ lowin,
               float* __restrict__ out)
{
    extern __shared__ __align__(16) float sA[];   // CROWS x NDIM pinned A rows

    const int p    = blockIdx.x;
    const int tid  = threadIdx.x;
    const int lane = tid & 31;
    const int w    = tid >> 5;

    __shared__ __align__(16) float s_x[NDIM];
    __shared__ __align__(16) float s_grad[NDIM];
    __shared__ __align__(16) float s_lo[NDIM];
    __shared__ __align__(16) float s_xr[NDIM];
    __shared__ __align__(16) float s_bw[MDIM];
    __shared__ __align__(16) float s_Ax[MDIM];
    __shared__ __align__(16) float s_Ag[MDIM];
    __shared__ __align__(16) float s_v[MDIM];
    __shared__ __align__(16) float s_gb[8 * NDIM];   // per-warp gbar partials
    __shared__ unsigned s_mask;
    __shared__ float    s_step;
    __shared__ int      s_feas;

    const float* A  = Ain  + (size_t)p * MDIM * NDIM;
    float*       Aw = g_Aw + (size_t)p * MDIM * NDIM;

    // Read sense BEFORE first arrive (all CTAs read pre-flip value).
    unsigned sense = *(volatile unsigned*)&g_sense;

    // CTA 0 re-initializes per-iteration barrier state each run (ordered by
    // setup barrier #0: writes -> threadfence -> arrive; others spin-acquire).
    if (p == 0) {
        if (tid < KITER) { g_and[tid] = MASK_ALL; g_cnt[tid] = 0u; }
        if (tid == 0)    g_rel = 0u;   // stale epochs can never match 1..KITER
    }

    if (tid < NDIM) {
        s_lo[tid] = lowin[p * NDIM + tid];
        s_xr[tid] = xraw[p * NDIM + tid];
    }
    if (tid == 0) s_feas = 1;
    __syncthreads();

    const int n0 = 4 * lane;
    const int n1 = 128 + 4 * lane;
    const float4 l0 = *(const float4*)(s_lo + n0);
    const float4 l1 = *(const float4*)(s_lo + n1);

    // per-lane line-search step: lane l tests step 2^-l (exact power of two)
    const float stepl = __uint_as_float((unsigned)(127 - lane) << 23);

    float* s_red = s_gb;   // alias: s_gb unused during setup

    // ---------------- setup: row-normalize, cache first 40 rows in smem -----
#pragma unroll 4
    for (int j = 0; j < 16; j++) {
        const int m = w + 8 * j;
        const float4 a0 = *(const float4*)(A + (size_t)m * NDIM + n0);
        const float4 a1 = *(const float4*)(A + (size_t)m * NDIM + n1);
        float ss = warp_allreduce_add(dot8(a0, a1, a0, a1));
        const float norm = fmaxf(sqrtf(ss), 1e-12f);
        float4 w0, w1;
        w0.x = a0.x / norm; w0.y = a0.y / norm; w0.z = a0.z / norm; w0.w = a0.w / norm;
        w1.x = a1.x / norm; w1.y = a1.y / norm; w1.z = a1.z / norm; w1.w = a1.w / norm;
        *(float4*)(Aw + (size_t)m * NDIM + n0) = w0;
        *(float4*)(Aw + (size_t)m * NDIM + n1) = w1;
        if (m < CROWS) {
            *(float4*)(sA + m * NDIM + n0) = w0;
            *(float4*)(sA + m * NDIM + n1) = w1;
        }
        float ad = (w0.x + w0.y + w0.z + w0.w) + (w1.x + w1.y + w1.z + w1.w);
        float sd = dot8(w0, w1, l0, l1);
        ad = warp_allreduce_add(ad);
        sd = warp_allreduce_add(sd);
        if (lane == 0) {
            const float bwm = bin[p * MDIM + m] / norm;
            s_bw[m]  = bwm;
            s_Ax[m]  = ad;          // temp: Ad
            s_red[m] = bwm - sd;    // temp: slack at lower
        }
    }
    __syncthreads();

    // t = max(0.5 * min_m ratio, 2*eps)
    if (tid < MDIM) {
        const float ad = s_Ax[tid];
        s_red[tid] = (ad > 0.f) ? (s_red[tid] / fmaxf(ad, 1e-12f))
                                : __int_as_float(0x7f800000); // +inf
    }
    __syncthreads();
    for (int off = 64; off >= 1; off >>= 1) {
        if (tid < off) s_red[tid] = fminf(s_red[tid], s_red[tid + off]);
        __syncthreads();
    }
    const float t = fmaxf(0.5f * s_red[0], 2.f * EPSF);
    __syncthreads();   // s_red (=s_gb) free again

    // feasibility of x = lower + t (fresh dots); also seeds s_Ax = A*x
    {
        float4 xq0, xq1;
        xq0.x = l0.x + t; xq0.y = l0.y + t; xq0.z = l0.z + t; xq0.w = l0.w + t;
        xq1.x = l1.x + t; xq1.y = l1.y + t; xq1.z = l1.z + t; xq1.w = l1.w + t;
#pragma unroll
        for (int j = 0; j < CJ; j++) {
            const int m = w + 8 * j;
            const float4 a0 = *(const float4*)(sA + m * NDIM + n0);
            const float4 a1 = *(const float4*)(sA + m * NDIM + n1);
            float d = warp_allreduce_add(dot8(a0, a1, xq0, xq1));
            if (lane == 0) {
                s_Ax[m] = d;
                if (!(d <= s_bw[m] - EPSF)) atomicAnd(&s_feas, 0);
            }
        }
#pragma unroll 4
        for (int j = CJ; j < 16; j++) {
            const int m = w + 8 * j;
            const float4 a0 = *(const float4*)(Aw + (size_t)m * NDIM + n0);
            const float4 a1 = *(const float4*)(Aw + (size_t)m * NDIM + n1);
            float d = warp_allreduce_add(dot8(a0, a1, xq0, xq1));
            if (lane == 0) {
                s_Ax[m] = d;
                if (!(d <= s_bw[m] - EPSF)) atomicAnd(&s_feas, 0);
            }
        }
        if (tid < NDIM) {
            const float xv = s_lo[tid] + t;
            if (!(xv >= s_lo[tid] + EPSF)) atomicAnd(&s_feas, 0);
        }
        __syncthreads();
        if (tid < NDIM) {
            float xv = s_lo[tid] + t;
            if (!s_feas) xv = 0.5f * (fmaxf(xv, 0.f) + s_lo[tid]);
            s_x[tid] = xv;
        }
        __syncthreads();
        if (!s_feas) {   // rare repair branch: recompute Ax of repaired x
            const float4 r0 = *(const float4*)(s_x + n0);
            const float4 r1 = *(const float4*)(s_x + n1);
            for (int j = 0; j < 16; j++) {
                const int m = w + 8 * j;
                const float* src = (j < CJ) ? (sA + m * NDIM)
                                            : (Aw + (size_t)m * NDIM);
                const float4 a0 = *(const float4*)(src + n0);
                const float4 a1 = *(const float4*)(src + n1);
                float d = warp_allreduce_add(dot8(a0, a1, r0, r1));
                if (lane == 0) s_Ax[m] = d;
            }
        }
    }

    GRID_BARRIER();   // barrier #0: barrier-state init + everyone's setup done

    // prime v and s_mask for iteration 0
    if (tid < MDIM)
        s_v[tid] = __fdividef(MUF, fmaxf(s_bw[tid] - s_Ax[tid], 1e-12f));
    if (tid == 0) s_mask = MASK_ALL;
    __syncthreads();

    // prime cross-barrier prefetch: pass G's first gmem row (j = CJ)
    ulonglong2 pf0 = *(const ulonglong2*)(Aw + (size_t)(w + 8 * CJ) * NDIM + n0);
    ulonglong2 pf1 = *(const ulonglong2*)(Aw + (size_t)(w + 8 * CJ) * NDIM + n1);

    // ---------------- main loop (incremental Ax: Ax_{k+1} = Ax_k - step*Ag) --
    for (int k = 0; k < KITER; k++) {
        // ---- pass G: gbar partials (pure streaming, no reduce/div) ---------
        u64 ga0 = 0ull, ga1 = 0ull, ga2 = 0ull, ga3 = 0ull;

#define PG_ROW(A0, A1, m)                                                     \
        do {                                                                  \
            const float v_ = s_v[m];                                          \
            const u64 vv = pack2(v_, v_);                                     \
            ga0 = fma2((A0).x, vv, ga0); ga1 = fma2((A0).y, vv, ga1);         \
            ga2 = fma2((A1).x, vv, ga2); ga3 = fma2((A1).y, vv, ga3);         \
        } while (0)

        // j = CJ from the cross-barrier prefetch (L2 latency hidden by spin)
        PG_ROW(pf0, pf1, w + 8 * CJ);
        // gmem rows j = CJ+1 .. 14
#pragma unroll 4
        for (int j = CJ + 1; j < 15; j++) {
            const int m = w + 8 * j;
            const ulonglong2 a0 = *(const ulonglong2*)(Aw + (size_t)m * NDIM + n0);
            const ulonglong2 a1 = *(const ulonglong2*)(Aw + (size_t)m * NDIM + n1);
            PG_ROW(a0, a1, m);
        }
        // j = 15 explicit: keep registers alive for pass A reuse
        const int m15 = w + 120;
        const ulonglong2 a15x = *(const ulonglong2*)(Aw + (size_t)m15 * NDIM + n0);
        const ulonglong2 a15y = *(const ulonglong2*)(Aw + (size_t)m15 * NDIM + n1);
        PG_ROW(a15x, a15y, m15);
        // smem-pinned rows
#pragma unroll
        for (int j = 0; j < CJ; j++) {
            const int m = w + 8 * j;
            const ulonglong2 a0 = *(const ulonglong2*)(sA + m * NDIM + n0);
            const ulonglong2 a1 = *(const ulonglong2*)(sA + m * NDIM + n1);
            PG_ROW(a0, a1, m);
        }
#undef PG_ROW

        {
            ulonglong2 t0; t0.x = ga0; t0.y = ga1;
            ulonglong2 t1; t1.x = ga2; t1.y = ga3;
            *(ulonglong2*)(s_gb + w * NDIM + n0) = t0;
            *(ulonglong2*)(s_gb + w * NDIM + n1) = t1;
        }
        __syncthreads();

        // grad + column-constraint mask bits (per-thread, serial + fast path)
        if (tid < NDIM) {
            float gb = 0.f;
#pragma unroll
            for (int j = 0; j < 8; j++) gb += s_gb[j * NDIM + tid];
            const float xv  = s_x[tid];
            const float lov = s_lo[tid];
            const float slo = fmaxf(xv - lov, 1e-12f);
            const float gr  = (xv - s_xr[tid]) + gb + __fdividef(MUF, slo);
            s_grad[tid] = gr;

            const float lim = lov + EPSF;
            if (!(gr <= 0.f && xv >= lim)) {   // fast path: all candidates pass
                unsigned mk = MASK_ALL;
                float st = 1.f;
#pragma unroll
                for (int l = 0; l < LMAX; l++) {
                    const float c = fmaf(-st, gr, xv);
                    if (!(c >= lim)) mk &= ~(1u << l);
                    st *= 0.5f;
                }
                if (mk != MASK_ALL) atomicAnd(&s_mask, mk);
            }
        }
        __syncthreads();

        // ---- pass A: Ag dots + row masks via lane-parallel ballot ----------
        const ulonglong2 gA = *(const ulonglong2*)(s_grad + n0);
        const ulonglong2 gB = *(const ulonglong2*)(s_grad + n1);
        unsigned wmask = MASK_ALL;

#define PA_ROW(A0, A1, m)                                                     \
        do {                                                                  \
            u64 s = mul2((A0).x, gA.x);                                       \
            s = fma2((A0).y, gA.y, s);                                        \
            s = fma2((A1).x, gB.x, s);                                        \
            s = fma2((A1).y, gB.y, s);                                        \
            float slo_, shi_; unpack2(s, slo_, shi_);                         \
            float ag = warp_allreduce_add(slo_ + shi_);                       \
            if (lane == 0) s_Ag[m] = ag;                                      \
            const float axc = fmaf(-stepl, ag, s_Ax[m]);                      \
            const unsigned bits =                                             \
                __ballot_sync(0xffffffffu, axc <= s_bw[m] - EPSF);            \
            wmask &= (bits | ~MASK_ALL);                                      \
        } while (0)

        // j = 15 from pass G's registers (no load at all)
        PA_ROW(a15x, a15y, m15);
        // gmem rows descending j = 14 .. CJ
#pragma unroll 4
        for (int j = 14; j >= CJ; j--) {
            const int m = w + 8 * j;
            const ulonglong2 a0 = *(const ulonglong2*)(Aw + (size_t)m * NDIM + n0);
            const ulonglong2 a1 = *(const ulonglong2*)(Aw + (size_t)m * NDIM + n1);
            PA_ROW(a0, a1, m);
        }
        // smem-pinned rows
#pragma unroll
        for (int j = 0; j < CJ; j++) {
            const int m = w + 8 * j;
            const ulonglong2 a0 = *(const ulonglong2*)(sA + m * NDIM + n0);
            const ulonglong2 a1 = *(const ulonglong2*)(sA + m * NDIM + n1);
            PA_ROW(a0, a1, m);
        }
#undef PA_ROW

        if (lane == 0 && wmask != MASK_ALL) atomicAnd(&s_mask, wmask);

        // cross-barrier prefetch for NEXT iteration's pass G (row j = CJ):
        // A is constant, so this load has no dependency and its L2 latency
        // hides under the global-barrier spin + syncs below.
        pf0 = *(const ulonglong2*)(Aw + (size_t)(w + 8 * CJ) * NDIM + n0);
        pf1 = *(const ulonglong2*)(Aw + (size_t)(w + 8 * CJ) * NDIM + n1);

        __syncthreads();

        // ---- flat global barrier; release word carries the step -------------
        if (tid == 0) {
            atomicAnd(&g_and[k], s_mask);
            __threadfence();
            if (atomicAdd(&g_cnt[k], 1u) == NPROB - 1u) {   // last arrival
                __threadfence();
                const unsigned fin = *(volatile unsigned*)&g_and[k] & MASK_ALL;
                const unsigned sb = fin ? (unsigned)(__ffs(fin) - 1) : 0xFFu;
                atomicExch(&g_rel, ((unsigned)(k + 1) << 8) | sb);
            }
            unsigned relv;
            while (((relv = *(volatile unsigned*)&g_rel) >> 8) != (unsigned)(k + 1))
                __nanosleep(32);
            const unsigned sb = relv & 0xFFu;
            s_step = (sb == 0xFFu) ? 0.f
                                   : __uint_as_float((127u - sb) << 23);
            s_mask = MASK_ALL;                // reset for next iteration
        }
        __syncthreads();

        // owner-thread updates: x, Ax, and v for the next iteration
        if (tid < NDIM) s_x[tid] = fmaf(-s_step, s_grad[tid], s_x[tid]);
        if (tid < MDIM) {
            const float nAx = fmaf(-s_step, s_Ag[tid], s_Ax[tid]);
            s_Ax[tid] = nAx;
            s_v[tid]  = __fdividef(MUF, fmaxf(s_bw[tid] - nAx, 1e-12f));
        }
        __syncthreads();   // s_v/s_x/s_mask visible to all for next iteration
    }

    // finalize: relu(x) -> out
    if (tid < NDIM) out[p * NDIM + tid] = fmaxf(s_x[tid], 0.f);
}

extern "C" void kernel_launch(void* const* d_in, const int* in_sizes, int n_in,
                              void* d_out, int out_size) {
    // Identify inputs by size (dict order: x_raw, A, b, lower).
    int iA = 1, ib = 2, iv1 = 0, iv2 = 3;
    {
        int big = -1, small = -1, v1 = -1, v2 = -1;
        for (int i = 0; i < n_in; i++) {
            if (in_sizes[i] == NPROB * MDIM * NDIM) big = i;
            else if (in_sizes[i] == NPROB * MDIM)   small = i;
            else if (v1 < 0) v1 = i;
            else             v2 = i;
        }
        if (big >= 0 && small >= 0 && v1 >= 0 && v2 >= 0) {
            iA = big; ib = small; iv1 = v1; iv2 = v2;
        }
    }
    const float* xr  = (const float*)d_in[iv1];
    const float* A   = (const float*)d_in[iA];
    const float* b   = (const float*)d_in[ib];
    const float* low = (const float*)d_in[iv2];
    float* out = (float*)d_out;

    // Opt-in: static (~14.9KB) + dynamic (40KB) > 48KB default per-block limit.
    // Not a stream-ordered call -> does not enter / invalidate graph capture.
    cudaFuncSetAttribute(persist_kernel,
                         cudaFuncAttributeMaxDynamicSharedMemorySize, DYNSMEM);

    persist_kernel<<<NPROB, TPB, DYNSMEM>>>(xr, A, b, low, out);
}

// round 14
// speedup vs baseline: 1.4044x; 1.0842x over previous
#include <cuda_runtime.h>
#include <cstdint>

#define NPROB 512            // B*S = 32*16
#define MDIM  128
#define NDIM  256
#define EPSF  1e-6f
#define MUF   0.01f
#define KITER 30
#define LMAX  25
#define MASK_ALL 0x01FFFFFFu // 25 bits
#define TPB   256
#define CJ    5              // cached row-groups per warp (rows 0..39 in smem)
#define CROWS (CJ * 8)       // 40 rows cached
#define DYNSMEM (CROWS * NDIM * 4)

typedef unsigned long long u64;

// Persistent device state
__device__ float    g_Aw[(size_t)NPROB * MDIM * NDIM]; // row-normalized A (64MB)
__device__ unsigned g_count;                            // setup barrier counter
__device__ unsigned g_sense;                            // setup barrier sense
__device__ unsigned g_and[KITER];                       // per-iter AND of masks
__device__ unsigned g_cnt[KITER];                       // per-iter arrival count
__device__ unsigned g_rel;                              // release: (epoch<<8)|stepbyte

// ---- packed f32x2 helpers (sm_103a FFMA2 path; per-element IEEE fp32) ----
__device__ __forceinline__ u64 pack2(float x, float y) {
    u64 r; asm("mov.b64 %0, {%1, %2};" : "=l"(r) : "f"(x), "f"(y)); return r;
}
__device__ __forceinline__ void unpack2(u64 v, float& x, float& y) {
    asm("mov.b64 {%0, %1}, %2;" : "=f"(x), "=f"(y) : "l"(v));
}
__device__ __forceinline__ u64 fma2(u64 a, u64 b, u64 c) {
    u64 d; asm("fma.rn.f32x2 %0, %1, %2, %3;" : "=l"(d) : "l"(a), "l"(b), "l"(c));
    return d;
}
__device__ __forceinline__ u64 mul2(u64 a, u64 b) {
    u64 d; asm("mul.rn.f32x2 %0, %1, %2;" : "=l"(d) : "l"(a), "l"(b));
    return d;
}

// NOTE: redux.sync.add.f32 is NOT supported on sm_103 (ptxas rejects it).
__device__ __forceinline__ float warp_allreduce_add(float v) {
#pragma unroll
    for (int o = 16; o; o >>= 1) v += __shfl_xor_sync(0xffffffffu, v, o);
    return v;
}

// Multi-row reduction: 8 independent 32-lane sums in 9 shfls.
// Row i's sum follows the SAME xor-16,8,4,2,1 pairing tree as
// warp_allreduce_add -> bit-identical results. After return, lane l holds
// the full sum of row r(l) = 4*bit4(l) + 2*bit3(l) + bit2(l); row i's sum
// therefore lives (replicated) in lanes 4i..4i+3.
__device__ __forceinline__ float mreduce8(const float V[8], int lane) {
    const bool lo16 = (lane & 16) == 0;
    float W[4];
#pragma unroll
    for (int i = 0; i < 4; i++) {
        const float send = lo16 ? V[i + 4] : V[i];
        const float keep = lo16 ? V[i]     : V[i + 4];
        W[i] = keep + __shfl_xor_sync(0xffffffffu, send, 16);
    }
    const bool lo8 = (lane & 8) == 0;
    float X[2];
#pragma unroll
    for (int i = 0; i < 2; i++) {
        const float send = lo8 ? W[i + 2] : W[i];
        const float keep = lo8 ? W[i]     : W[i + 2];
        X[i] = keep + __shfl_xor_sync(0xffffffffu, send, 8);
    }
    const bool lo4 = (lane & 4) == 0;
    {
        const float send = lo4 ? X[1] : X[0];
        const float keep = lo4 ? X[0] : X[1];
        float Y = keep + __shfl_xor_sync(0xffffffffu, send, 4);
        Y += __shfl_xor_sync(0xffffffffu, Y, 2);
        Y += __shfl_xor_sync(0xffffffffu, Y, 1);
        return Y;
    }
}

__device__ __forceinline__ float dot8(float4 a0, float4 a1, float4 b0, float4 b1) {
    float s = a0.x * b0.x + a0.y * b0.y + a0.z * b0.z + a0.w * b0.w;
    s += a1.x * b1.x + a1.y * b1.y + a1.z * b1.z + a1.w * b1.w;
    return s;
}

// Setup-only grid barrier (runs once). All NPROB CTAs co-resident:
// __launch_bounds__(256,4) + ~55KB smem/CTA -> 4 CTAs/SM * 148 = 592 >= 512.
#define GRID_BARRIER()                                                        \
    do {                                                                      \
        __syncthreads();                                                      \
        if (tid == 0) {                                                       \
            const unsigned target = sense ^ 1u;                               \
            __threadfence();                                                  \
            if (atomicAdd(&g_count, 1u) == NPROB - 1u) {                      \
                atomicExch(&g_count, 0u);                                     \
                __threadfence();                                              \
                atomicExch(&g_sense, target);                                 \
            } else {                                                          \
                while (*(volatile unsigned*)&g_sense != target)               \
                    __nanosleep(64);                                          \
            }                                                                 \
            sense = target;                                                   \
            __threadfence();                                                  \
        }                                                                     \
        __syncthreads();                                                      \
    } while (0)

__global__ void __launch_bounds__(TPB, 4)
persist_kernel(const float* __restrict__ xraw,
               const float* __restrict__ Ain,
               const float* __restrict__ bin,
               const float* __restrict__ lowin,
               float* __restrict__ out)
{
    extern __shared__ __align__(16) float sA[];   // CROWS x NDIM pinned A rows

    const int p    = blockIdx.x;
    const int tid  = threadIdx.x;
    const int lane = tid & 31;
    const int w    = tid >> 5;

    __shared__ __align__(16) float s_x[NDIM];
    __shared__ __align__(16) float s_grad[NDIM];
    __shared__ __align__(16) float s_lo[NDIM];
    __shared__ __align__(16) float s_xr[NDIM];
    __shared__ __align__(16) float s_bw[MDIM];
    __shared__ __align__(16) float s_Ax[MDIM];
    __shared__ __align__(16) float s_Ag[MDIM];
    __shared__ __align__(16) float s_v[MDIM];
    __shared__ __align__(16) float s_gb[8 * NDIM];   // per-warp gbar partials
    __shared__ unsigned s_mask;
    __shared__ float    s_step;
    __shared__ int      s_feas;

    const float* A  = Ain  + (size_t)p * MDIM * NDIM;
    float*       Aw = g_Aw + (size_t)p * MDIM * NDIM;

    // Read sense BEFORE first arrive (all CTAs read pre-flip value).
    unsigned sense = *(volatile unsigned*)&g_sense;

    // CTA 0 re-initializes per-iteration barrier state each run (ordered by
    // setup barrier #0: writes -> threadfence -> arrive; others spin-acquire).
    if (p == 0) {
        if (tid < KITER) { g_and[tid] = MASK_ALL; g_cnt[tid] = 0u; }
        if (tid == 0)    g_rel = 0u;   // stale epochs can never match 1..KITER
    }

    if (tid < NDIM) {
        s_lo[tid] = lowin[p * NDIM + tid];
        s_xr[tid] = xraw[p * NDIM + tid];
    }
    if (tid == 0) s_feas = 1;
    __syncthreads();

    const int n0 = 4 * lane;
    const int n1 = 128 + 4 * lane;
    const float4 l0 = *(const float4*)(s_lo + n0);
    const float4 l1 = *(const float4*)(s_lo + n1);

    // per-lane line-search step: lane l tests step 2^-l (exact power of two)
    const float stepl = __uint_as_float((unsigned)(127 - lane) << 23);

    float* s_red = s_gb;   // alias: s_gb unused during setup

    // ---------------- setup: row-normalize, cache first 40 rows in smem -----
#pragma unroll 4
    for (int j = 0; j < 16; j++) {
        const int m = w + 8 * j;
        const float4 a0 = *(const float4*)(A + (size_t)m * NDIM + n0);
        const float4 a1 = *(const float4*)(A + (size_t)m * NDIM + n1);
        float ss = warp_allreduce_add(dot8(a0, a1, a0, a1));
        const float norm = fmaxf(sqrtf(ss), 1e-12f);
        float4 w0, w1;
        w0.x = a0.x / norm; w0.y = a0.y / norm; w0.z = a0.z / norm; w0.w = a0.w / norm;
        w1.x = a1.x / norm; w1.y = a1.y / norm; w1.z = a1.z / norm; w1.w = a1.w / norm;
        *(float4*)(Aw + (size_t)m * NDIM + n0) = w0;
        *(float4*)(Aw + (size_t)m * NDIM + n1) = w1;
        if (m < CROWS) {
            *(float4*)(sA + m * NDIM + n0) = w0;
            *(float4*)(sA + m * NDIM + n1) = w1;
        }
        float ad = (w0.x + w0.y + w0.z + w0.w) + (w1.x + w1.y + w1.z + w1.w);
        float sd = dot8(w0, w1, l0, l1);
        ad = warp_allreduce_add(ad);
        sd = warp_allreduce_add(sd);
        if (lane == 0) {
            const float bwm = bin[p * MDIM + m] / norm;
            s_bw[m]  = bwm;
            s_Ax[m]  = ad;          // temp: Ad
            s_red[m] = bwm - sd;    // temp: slack at lower
        }
    }
    __syncthreads();

    // t = max(0.5 * min_m ratio, 2*eps)
    if (tid < MDIM) {
        const float ad = s_Ax[tid];
        s_red[tid] = (ad > 0.f) ? (s_red[tid] / fmaxf(ad, 1e-12f))
                                : __int_as_float(0x7f800000); // +inf
    }
    __syncthreads();
    for (int off = 64; off >= 1; off >>= 1) {
        if (tid < off) s_red[tid] = fminf(s_red[tid], s_red[tid + off]);
        __syncthreads();
    }
    const float t = fmaxf(0.5f * s_red[0], 2.f * EPSF);
    __syncthreads();   // s_red (=s_gb) free again

    // feasibility of x = lower + t (fresh dots); also seeds s_Ax = A*x
    {
        float4 xq0, xq1;
        xq0.x = l0.x + t; xq0.y = l0.y + t; xq0.z = l0.z + t; xq0.w = l0.w + t;
        xq1.x = l1.x + t; xq1.y = l1.y + t; xq1.z = l1.z + t; xq1.w = l1.w + t;
#pragma unroll
        for (int j = 0; j < CJ; j++) {
            const int m = w + 8 * j;
            const float4 a0 = *(const float4*)(sA + m * NDIM + n0);
            const float4 a1 = *(const float4*)(sA + m * NDIM + n1);
            float d = warp_allreduce_add(dot8(a0, a1, xq0, xq1));
            if (lane == 0) {
                s_Ax[m] = d;
                if (!(d <= s_bw[m] - EPSF)) atomicAnd(&s_feas, 0);
            }
        }
#pragma unroll 4
        for (int j = CJ; j < 16; j++) {
            const int m = w + 8 * j;
            const float4 a0 = *(const float4*)(Aw + (size_t)m * NDIM + n0);
            const float4 a1 = *(const float4*)(Aw + (size_t)m * NDIM + n1);
            float d = warp_allreduce_add(dot8(a0, a1, xq0, xq1));
            if (lane == 0) {
                s_Ax[m] = d;
                if (!(d <= s_bw[m] - EPSF)) atomicAnd(&s_feas, 0);
            }
        }
        if (tid < NDIM) {
            const float xv = s_lo[tid] + t;
            if (!(xv >= s_lo[tid] + EPSF)) atomicAnd(&s_feas, 0);
        }
        __syncthreads();
        if (tid < NDIM) {
            float xv = s_lo[tid] + t;
            if (!s_feas) xv = 0.5f * (fmaxf(xv, 0.f) + s_lo[tid]);
            s_x[tid] = xv;
        }
        __syncthreads();
        if (!s_feas) {   // rare repair branch: recompute Ax of repaired x
            const float4 r0 = *(const float4*)(s_x + n0);
            const float4 r1 = *(const float4*)(s_x + n1);
            for (int j = 0; j < 16; j++) {
                const int m = w + 8 * j;
                const float* src = (j < CJ) ? (sA + m * NDIM)
                                            : (Aw + (size_t)m * NDIM);
                const float4 a0 = *(const float4*)(src + n0);
                const float4 a1 = *(const float4*)(src + n1);
                float d = warp_allreduce_add(dot8(a0, a1, r0, r1));
                if (lane == 0) s_Ax[m] = d;
            }
        }
    }

    GRID_BARRIER();   // barrier #0: barrier-state init + everyone's setup done

    // prime v and s_mask for iteration 0
    if (tid < MDIM)
        s_v[tid] = __fdividef(MUF, fmaxf(s_bw[tid] - s_Ax[tid], 1e-12f));
    if (tid == 0) s_mask = MASK_ALL;
    __syncthreads();

    // prime cross-barrier prefetch: pass G's first gmem row (j = CJ)
    ulonglong2 pf0 = *(const ulonglong2*)(Aw + (size_t)(w + 8 * CJ) * NDIM + n0);
    ulonglong2 pf1 = *(const ulonglong2*)(Aw + (size_t)(w + 8 * CJ) * NDIM + n1);

    // ---------------- main loop (incremental Ax: Ax_{k+1} = Ax_k - step*Ag) --
    for (int k = 0; k < KITER; k++) {
        // ---- pass G: gbar partials (pure streaming, no reduce/div) ---------
        u64 ga0 = 0ull, ga1 = 0ull, ga2 = 0ull, ga3 = 0ull;

#define PG_ROW(A0, A1, m)                                                     \
        do {                                                                  \
            const float v_ = s_v[m];                                          \
            const u64 vv = pack2(v_, v_);                                     \
            ga0 = fma2((A0).x, vv, ga0); ga1 = fma2((A0).y, vv, ga1);         \
            ga2 = fma2((A1).x, vv, ga2); ga3 = fma2((A1).y, vv, ga3);         \
        } while (0)

        // j = CJ from the cross-barrier prefetch (L2 latency hidden by spin)
        PG_ROW(pf0, pf1, w + 8 * CJ);
        // gmem rows j = CJ+1 .. 15
#pragma unroll 4
        for (int j = CJ + 1; j < 16; j++) {
            const int m = w + 8 * j;
            const ulonglong2 a0 = *(const ulonglong2*)(Aw + (size_t)m * NDIM + n0);
            const ulonglong2 a1 = *(const ulonglong2*)(Aw + (size_t)m * NDIM + n1);
            PG_ROW(a0, a1, m);
        }
        // smem-pinned rows
#pragma unroll
        for (int j = 0; j < CJ; j++) {
            const int m = w + 8 * j;
            const ulonglong2 a0 = *(const ulonglong2*)(sA + m * NDIM + n0);
            const ulonglong2 a1 = *(const ulonglong2*)(sA + m * NDIM + n1);
            PG_ROW(a0, a1, m);
        }
#undef PG_ROW

        {
            ulonglong2 t0; t0.x = ga0; t0.y = ga1;
            ulonglong2 t1; t1.x = ga2; t1.y = ga3;
            *(ulonglong2*)(s_gb + w * NDIM + n0) = t0;
            *(ulonglong2*)(s_gb + w * NDIM + n1) = t1;
        }
        __syncthreads();

        // grad + column-constraint mask bits (per-thread, serial + fast path)
        if (tid < NDIM) {
            float gb = 0.f;
#pragma unroll
            for (int j = 0; j < 8; j++) gb += s_gb[j * NDIM + tid];
            const float xv  = s_x[tid];
            const float lov = s_lo[tid];
            const float slo = fmaxf(xv - lov, 1e-12f);
            const float gr  = (xv - s_xr[tid]) + gb + __fdividef(MUF, slo);
            s_grad[tid] = gr;

            const float lim = lov + EPSF;
            if (!(gr <= 0.f && xv >= lim)) {   // fast path: all candidates pass
                unsigned mk = MASK_ALL;
                float st = 1.f;
#pragma unroll
                for (int l = 0; l < LMAX; l++) {
                    const float c = fmaf(-st, gr, xv);
                    if (!(c >= lim)) mk &= ~(1u << l);
                    st *= 0.5f;
                }
                if (mk != MASK_ALL) atomicAnd(&s_mask, mk);
            }
        }
        __syncthreads();

        // ---- pass A: Ag dots (8-row batched butterfly) + ballot row masks ---
        const ulonglong2 gA = *(const ulonglong2*)(s_grad + n0);
        const ulonglong2 gB = *(const ulonglong2*)(s_grad + n1);
        unsigned wmask = MASK_ALL;
        const int rrow = ((lane >> 4) & 1) * 4 + ((lane >> 3) & 1) * 2
                       + ((lane >> 2) & 1);   // row index this lane's sum maps to

#define PA_DOT(A0, A1, dst)                                                   \
        do {                                                                  \
            u64 s_ = mul2((A0).x, gA.x);                                      \
            s_ = fma2((A0).y, gA.y, s_);                                      \
            s_ = fma2((A1).x, gB.x, s_);                                      \
            s_ = fma2((A1).y, gB.y, s_);                                      \
            float sl_, sh_; unpack2(s_, sl_, sh_);                            \
            dst = sl_ + sh_;                                                  \
        } while (0)

        {
            // batch 1: rows j = 8..15 (gmem)
            float prt[8];
#pragma unroll
            for (int i = 0; i < 8; i++) {
                const int m = w + 8 * (8 + i);
                const ulonglong2 a0 = *(const ulonglong2*)(Aw + (size_t)m * NDIM + n0);
                const ulonglong2 a1 = *(const ulonglong2*)(Aw + (size_t)m * NDIM + n1);
                PA_DOT(a0, a1, prt[i]);
            }
            const float S = mreduce8(prt, lane);
            if ((lane & 3) == 0) s_Ag[w + 8 * (8 + rrow)] = S;
#pragma unroll
            for (int i = 0; i < 8; i++) {
                const float ag = __shfl_sync(0xffffffffu, S, 4 * i);
                const int m = w + 8 * (8 + i);
                const float axc = fmaf(-stepl, ag, s_Ax[m]);
                const unsigned bits =
                    __ballot_sync(0xffffffffu, axc <= s_bw[m] - EPSF);
                wmask &= (bits | ~MASK_ALL);
            }
        }
        {
            // batch 2: rows j = 0..7 (pinned j<CJ, gmem j>=CJ; compile-time select)
            float prt[8];
#pragma unroll
            for (int i = 0; i < 8; i++) {
                const int m = w + 8 * i;
                const float* src = (i < CJ) ? (sA + m * NDIM)
                                            : (Aw + (size_t)m * NDIM);
                const ulonglong2 a0 = *(const ulonglong2*)(src + n0);
                const ulonglong2 a1 = *(const ulonglong2*)(src + n1);
                PA_DOT(a0, a1, prt[i]);
            }
            const float S = mreduce8(prt, lane);
            if ((lane & 3) == 0) s_Ag[w + 8 * rrow] = S;
#pragma unroll
            for (int i = 0; i < 8; i++) {
                const float ag = __shfl_sync(0xffffffffu, S, 4 * i);
                const int m = w + 8 * i;
                const float axc = fmaf(-stepl, ag, s_Ax[m]);
                const unsigned bits =
                    __ballot_sync(0xffffffffu, axc <= s_bw[m] - EPSF);
                wmask &= (bits | ~MASK_ALL);
            }
        }
#undef PA_DOT

        if (lane == 0 && wmask != MASK_ALL) atomicAnd(&s_mask, wmask);

        // cross-barrier prefetch for NEXT iteration's pass G (row j = CJ):
        // A is constant -> no dependency; L2 latency hides under the spin.
        pf0 = *(const ulonglong2*)(Aw + (size_t)(w + 8 * CJ) * NDIM + n0);
        pf1 = *(const ulonglong2*)(Aw + (size_t)(w + 8 * CJ) * NDIM + n1);

        __syncthreads();

        // ---- flat global barrier; release word carries the step -------------
        if (tid == 0) {
            atomicAnd(&g_and[k], s_mask);
            __threadfence();
            if (atomicAdd(&g_cnt[k], 1u) == NPROB - 1u) {   // last arrival
                __threadfence();
                const unsigned fin = *(volatile unsigned*)&g_and[k] & MASK_ALL;
                const unsigned sb = fin ? (unsigned)(__ffs(fin) - 1) : 0xFFu;
                atomicExch(&g_rel, ((unsigned)(k + 1) << 8) | sb);
            }
            unsigned relv;
            while (((relv = *(volatile unsigned*)&g_rel) >> 8) != (unsigned)(k + 1))
                __nanosleep(32);
            const unsigned sb = relv & 0xFFu;
            s_step = (sb == 0xFFu) ? 0.f
                                   : __uint_as_float((127u - sb) << 23);
            s_mask = MASK_ALL;                // reset for next iteration
        }
        __syncthreads();

        // owner-thread updates: x, Ax, and v for the next iteration
        if (tid < NDIM) s_x[tid] = fmaf(-s_step, s_grad[tid], s_x[tid]);
        if (tid < MDIM) {
            const float nAx = fmaf(-s_step, s_Ag[tid], s_Ax[tid]);
            s_Ax[tid] = nAx;
            s_v[tid]  = __fdividef(MUF, fmaxf(s_bw[tid] - nAx, 1e-12f));
        }
        __syncthreads();   // s_v/s_x/s_mask visible to all for next iteration
    }

    // finalize: relu(x) -> out
    if (tid < NDIM) out[p * NDIM + tid] = fmaxf(s_x[tid], 0.f);
}

extern "C" void kernel_launch(void* const* d_in, const int* in_sizes, int n_in,
                              void* d_out, int out_size) {
    // Identify inputs by size (dict order: x_raw, A, b, lower).
    int iA = 1, ib = 2, iv1 = 0, iv2 = 3;
    {
        int big = -1, small = -1, v1 = -1, v2 = -1;
        for (int i = 0; i < n_in; i++) {
            if (in_sizes[i] == NPROB * MDIM * NDIM) big = i;
            else if (in_sizes[i] == NPROB * MDIM)   small = i;
            else if (v1 < 0) v1 = i;
            else             v2 = i;
        }
        if (big >= 0 && small >= 0 && v1 >= 0 && v2 >= 0) {
            iA = big; ib = small; iv1 = v1; iv2 = v2;
        }
    }
    const float* xr  = (const float*)d_in[iv1];
    const float* A   = (const float*)d_in[iA];
    const float* b   = (const float*)d_in[ib];
    const float* low = (const float*)d_in[iv2];
    float* out = (float*)d_out;

    // Opt-in: static (~14.9KB) + dynamic (40KB) > 48KB default per-block limit.
    // Not a stream-ordered call -> does not enter / invalidate graph capture.
    cudaFuncSetAttribute(persist_kernel,
                         cudaFuncAttributeMaxDynamicSharedMemorySize, DYNSMEM);

    persist_kernel<<<NPROB, TPB, DYNSMEM>>>(xr, A, b, low, out);
}

// round 15
// speedup vs baseline: 3.6819x; 2.6218x over previous
#include <cuda_runtime.h>
#include <cstdint>

#define NPROB 512            // B*S = 32*16
#define MDIM  128
#define NDIM  256
#define EPSF  1e-6f
#define MUF   0.01f
#define KITER 30
#define LMAX  25
#define MASK_ALL 0x01FFFFFFu // 25 bits
#define TPB   256
#define CJ    5              // full pinned row-groups (rows 0..39)
#define CROWS 44             // rows 0..43 pinned (row 40+w pinned for warps 0..3)
#define DYNSMEM (CROWS * NDIM * 4)   // 45056 B

typedef unsigned long long u64;

// Persistent device state
__device__ float    g_Aw[(size_t)NPROB * MDIM * NDIM]; // row-normalized A (64MB)
__device__ unsigned g_count;                            // setup barrier counter
__device__ unsigned g_sense;                            // setup barrier sense
__device__ unsigned g_and[KITER];                       // per-iter AND of masks
__device__ unsigned g_cnt[KITER];                       // per-iter arrival count
__device__ unsigned g_rel;                              // release: (epoch<<8)|stepbyte

// ---- packed f32x2 helpers (sm_103a FFMA2 path; per-element IEEE fp32) ----
__device__ __forceinline__ u64 pack2(float x, float y) {
    u64 r; asm("mov.b64 %0, {%1, %2};" : "=l"(r) : "f"(x), "f"(y)); return r;
}
__device__ __forceinline__ void unpack2(u64 v, float& x, float& y) {
    asm("mov.b64 {%0, %1}, %2;" : "=f"(x), "=f"(y) : "l"(v));
}
__device__ __forceinline__ u64 fma2(u64 a, u64 b, u64 c) {
    u64 d; asm("fma.rn.f32x2 %0, %1, %2, %3;" : "=l"(d) : "l"(a), "l"(b), "l"(c));
    return d;
}
__device__ __forceinline__ u64 mul2(u64 a, u64 b) {
    u64 d; asm("mul.rn.f32x2 %0, %1, %2;" : "=l"(d) : "l"(a), "l"(b));
    return d;
}
__device__ __forceinline__ u64 add2(u64 a, u64 b) {
    u64 d; asm("add.rn.f32x2 %0, %1, %2;" : "=l"(d) : "l"(a), "l"(b));
    return d;
}

// NOTE: redux.sync.add.f32 is NOT supported on sm_103 (ptxas rejects it).
__device__ __forceinline__ float warp_allreduce_add(float v) {
#pragma unroll
    for (int o = 16; o; o >>= 1) v += __shfl_xor_sync(0xffffffffu, v, o);
    return v;
}

// Multi-row reduction: 8 independent 32-lane sums in 9 shfls.
// Row i's sum follows the SAME xor-16,8,4,2,1 pairing tree as
// warp_allreduce_add -> bit-identical results. Row i's sum lives
// (replicated) in lanes 4i..4i+3.
__device__ __forceinline__ float mreduce8(const float V[8], int lane) {
    const bool lo16 = (lane & 16) == 0;
    float W[4];
#pragma unroll
    for (int i = 0; i < 4; i++) {
        const float send = lo16 ? V[i + 4] : V[i];
        const float keep = lo16 ? V[i]     : V[i + 4];
        W[i] = keep + __shfl_xor_sync(0xffffffffu, send, 16);
    }
    const bool lo8 = (lane & 8) == 0;
    float X[2];
#pragma unroll
    for (int i = 0; i < 2; i++) {
        const float send = lo8 ? W[i + 2] : W[i];
        const float keep = lo8 ? W[i]     : W[i + 2];
        X[i] = keep + __shfl_xor_sync(0xffffffffu, send, 8);
    }
    const bool lo4 = (lane & 4) == 0;
    {
        const float send = lo4 ? X[1] : X[0];
        const float keep = lo4 ? X[0] : X[1];
        float Y = keep + __shfl_xor_sync(0xffffffffu, send, 4);
        Y += __shfl_xor_sync(0xffffffffu, Y, 2);
        Y += __shfl_xor_sync(0xffffffffu, Y, 1);
        return Y;
    }
}

__device__ __forceinline__ float dot8(float4 a0, float4 a1, float4 b0, float4 b1) {
    float s = a0.x * b0.x + a0.y * b0.y + a0.z * b0.z + a0.w * b0.w;
    s += a1.x * b1.x + a1.y * b1.y + a1.z * b1.z + a1.w * b1.w;
    return s;
}

// Setup-only grid barrier (runs once). All NPROB CTAs co-resident:
// __launch_bounds__(256,4) + ~54KB smem/CTA -> 4 CTAs/SM * 148 = 592 >= 512.
#define GRID_BARRIER()                                                        \
    do {                                                                      \
        __syncthreads();                                                      \
        if (tid == 0) {                                                       \
            const unsigned target = sense ^ 1u;                               \
            __threadfence();                                                  \
            if (atomicAdd(&g_count, 1u) == NPROB - 1u) {                      \
                atomicExch(&g_count, 0u);                                     \
                __threadfence();                                              \
                atomicExch(&g_sense, target);                                 \
            } else {                                                          \
                while (*(volatile unsigned*)&g_sense != target)               \
                    __nanosleep(64);                                          \
            }                                                                 \
            sense = target;                                                   \
            __threadfence();                                                  \
        }                                                                     \
        __syncthreads();                                                      \
    } while (0)

__global__ void __launch_bounds__(TPB, 4)
persist_kernel(const float* __restrict__ xraw,
               const float* __restrict__ Ain,
               const float* __restrict__ bin,
               const float* __restrict__ lowin,
               float* __restrict__ out)
{
    extern __shared__ __align__(16) float sA[];   // CROWS x NDIM pinned A rows

    const int p    = blockIdx.x;
    const int tid  = threadIdx.x;
    const int lane = tid & 31;
    const int w    = tid >> 5;

    __shared__ __align__(16) float s_x[NDIM];
    __shared__ __align__(16) float s_grad[NDIM];
    __shared__ __align__(16) float s_lo[NDIM];
    __shared__ __align__(16) float s_xr[NDIM];
    __shared__ __align__(16) float s_bw[MDIM];
    __shared__ __align__(16) float s_Ax[MDIM];
    __shared__ __align__(16) float s_Ag[MDIM];
    __shared__ __align__(16) float s_v[MDIM];
    __shared__ __align__(16) float s_gb[4 * NDIM];   // merged gbar partials (4KB)
    __shared__ unsigned s_mask;
    __shared__ float    s_step;
    __shared__ int      s_feas;

    const float* A  = Ain  + (size_t)p * MDIM * NDIM;
    float*       Aw = g_Aw + (size_t)p * MDIM * NDIM;

    // Read sense BEFORE first arrive (all CTAs read pre-flip value).
    unsigned sense = *(volatile unsigned*)&g_sense;

    if (p == 0) {
        if (tid < KITER) { g_and[tid] = MASK_ALL; g_cnt[tid] = 0u; }
        if (tid == 0)    g_rel = 0u;   // stale epochs can never match 1..KITER
    }

    if (tid < NDIM) {
        s_lo[tid] = lowin[p * NDIM + tid];
        s_xr[tid] = xraw[p * NDIM + tid];
    }
    if (tid == 0) s_feas = 1;
    __syncthreads();

    const int n0 = 4 * lane;
    const int n1 = 128 + 4 * lane;
    const float4 l0 = *(const float4*)(s_lo + n0);
    const float4 l1 = *(const float4*)(s_lo + n1);

    // per-lane line-search step: lane l tests step 2^-l (exact power of two)
    const float stepl = __uint_as_float((unsigned)(127 - lane) << 23);

    float* s_red = s_gb;   // alias: s_gb unused during setup (>= MDIM floats)

    // ---------------- setup: row-normalize, cache first 44 rows in smem -----
#pragma unroll 4
    for (int j = 0; j < 16; j++) {
        const int m = w + 8 * j;
        const float4 a0 = *(const float4*)(A + (size_t)m * NDIM + n0);
        const float4 a1 = *(const float4*)(A + (size_t)m * NDIM + n1);
        float ss = warp_allreduce_add(dot8(a0, a1, a0, a1));
        const float norm = fmaxf(sqrtf(ss), 1e-12f);
        float4 w0, w1;
        w0.x = a0.x / norm; w0.y = a0.y / norm; w0.z = a0.z / norm; w0.w = a0.w / norm;
        w1.x = a1.x / norm; w1.y = a1.y / norm; w1.z = a1.z / norm; w1.w = a1.w / norm;
        *(float4*)(Aw + (size_t)m * NDIM + n0) = w0;
        *(float4*)(Aw + (size_t)m * NDIM + n1) = w1;
        if (m < CROWS) {
            *(float4*)(sA + m * NDIM + n0) = w0;
            *(float4*)(sA + m * NDIM + n1) = w1;
        }
        float ad = (w0.x + w0.y + w0.z + w0.w) + (w1.x + w1.y + w1.z + w1.w);
        float sd = dot8(w0, w1, l0, l1);
        ad = warp_allreduce_add(ad);
        sd = warp_allreduce_add(sd);
        if (lane == 0) {
            const float bwm = bin[p * MDIM + m] / norm;
            s_bw[m]  = bwm;
            s_Ax[m]  = ad;          // temp: Ad
            s_red[m] = bwm - sd;    // temp: slack at lower
        }
    }
    __syncthreads();

    // t = max(0.5 * min_m ratio, 2*eps)
    if (tid < MDIM) {
        const float ad = s_Ax[tid];
        s_red[tid] = (ad > 0.f) ? (s_red[tid] / fmaxf(ad, 1e-12f))
                                : __int_as_float(0x7f800000); // +inf
    }
    __syncthreads();
    for (int off = 64; off >= 1; off >>= 1) {
        if (tid < off) s_red[tid] = fminf(s_red[tid], s_red[tid + off]);
        __syncthreads();
    }
    const float t = fmaxf(0.5f * s_red[0], 2.f * EPSF);
    __syncthreads();   // s_red (=s_gb) free again

    // feasibility of x = lower + t (fresh dots); also seeds s_Ax = A*x
    {
        float4 xq0, xq1;
        xq0.x = l0.x + t; xq0.y = l0.y + t; xq0.z = l0.z + t; xq0.w = l0.w + t;
        xq1.x = l1.x + t; xq1.y = l1.y + t; xq1.z = l1.z + t; xq1.w = l1.w + t;
#pragma unroll
        for (int j = 0; j < CJ; j++) {
            const int m = w + 8 * j;
            const float4 a0 = *(const float4*)(sA + m * NDIM + n0);
            const float4 a1 = *(const float4*)(sA + m * NDIM + n1);
            float d = warp_allreduce_add(dot8(a0, a1, xq0, xq1));
            if (lane == 0) {
                s_Ax[m] = d;
                if (!(d <= s_bw[m] - EPSF)) atomicAnd(&s_feas, 0);
            }
        }
#pragma unroll 4
        for (int j = CJ; j < 16; j++) {
            const int m = w + 8 * j;
            const float4 a0 = *(const float4*)(Aw + (size_t)m * NDIM + n0);
            const float4 a1 = *(const float4*)(Aw + (size_t)m * NDIM + n1);
            float d = warp_allreduce_add(dot8(a0, a1, xq0, xq1));
            if (lane == 0) {
                s_Ax[m] = d;
                if (!(d <= s_bw[m] - EPSF)) atomicAnd(&s_feas, 0);
            }
        }
        if (tid < NDIM) {
            const float xv = s_lo[tid] + t;
            if (!(xv >= s_lo[tid] + EPSF)) atomicAnd(&s_feas, 0);
        }
        __syncthreads();
        if (tid < NDIM) {
            float xv = s_lo[tid] + t;
            if (!s_feas) xv = 0.5f * (fmaxf(xv, 0.f) + s_lo[tid]);
            s_x[tid] = xv;
        }
        __syncthreads();
        if (!s_feas) {   // rare repair branch: recompute Ax of repaired x
            const float4 r0 = *(const float4*)(s_x + n0);
            const float4 r1 = *(const float4*)(s_x + n1);
            for (int j = 0; j < 16; j++) {
                const int m = w + 8 * j;
                const float* src = (m < CROWS) ? (sA + m * NDIM)
                                               : (Aw + (size_t)m * NDIM);
                const float4 a0 = *(const float4*)(src + n0);
                const float4 a1 = *(const float4*)(src + n1);
                float d = warp_allreduce_add(dot8(a0, a1, r0, r1));
                if (lane == 0) s_Ax[m] = d;
            }
        }
    }

    GRID_BARRIER();   // barrier #0: barrier-state init + everyone's setup done

    // prime v and s_mask for iteration 0
    if (tid < MDIM)
        s_v[tid] = __fdividef(MUF, fmaxf(s_bw[tid] - s_Ax[tid], 1e-12f));
    if (tid == 0) s_mask = MASK_ALL;
    __syncthreads();

    // prime cross-barrier prefetch: pass G's first all-warp gmem row (j = 6)
    ulonglong2 pf0 = *(const ulonglong2*)(Aw + (size_t)(w + 48) * NDIM + n0);
    ulonglong2 pf1 = *(const ulonglong2*)(Aw + (size_t)(w + 48) * NDIM + n1);

    // ---------------- main loop (incremental Ax: Ax_{k+1} = Ax_k - step*Ag) --
    for (int k = 0; k < KITER; k++) {
        // ---- pass G: gbar partials (pure streaming, no reduce/div) ---------
        u64 ga0 = 0ull, ga1 = 0ull, ga2 = 0ull, ga3 = 0ull;

#define PG_ROW(A0, A1, m)                                                     \
        do {                                                                  \
            const float v_ = s_v[m];                                          \
            const u64 vv = pack2(v_, v_);                                     \
            ga0 = fma2((A0).x, vv, ga0); ga1 = fma2((A0).y, vv, ga1);         \
            ga2 = fma2((A1).x, vv, ga2); ga3 = fma2((A1).y, vv, ga3);         \
        } while (0)

        // j = 6 from the cross-barrier prefetch (L2 latency hidden by spin)
        PG_ROW(pf0, pf1, w + 48);
        // j = 5: pinned for warps 0-3, gmem for warps 4-7 (uniform select)
        {
            const int m5 = w + 40;
            const float* s5 = (w < 4) ? (sA + m5 * NDIM)
                                      : (Aw + (size_t)m5 * NDIM);
            const ulonglong2 a0 = *(const ulonglong2*)(s5 + n0);
            const ulonglong2 a1 = *(const ulonglong2*)(s5 + n1);
            PG_ROW(a0, a1, m5);
        }
        // gmem rows j = 7 .. 15
#pragma unroll 4
        for (int j = 7; j < 16; j++) {
            const int m = w + 8 * j;
            const ulonglong2 a0 = *(const ulonglong2*)(Aw + (size_t)m * NDIM + n0);
            const ulonglong2 a1 = *(const ulonglong2*)(Aw + (size_t)m * NDIM + n1);
            PG_ROW(a0, a1, m);
        }
        // fully-pinned rows j = 0..4
#pragma unroll
        for (int j = 0; j < CJ; j++) {
            const int m = w + 8 * j;
            const ulonglong2 a0 = *(const ulonglong2*)(sA + m * NDIM + n0);
            const ulonglong2 a1 = *(const ulonglong2*)(sA + m * NDIM + n1);
            PG_ROW(a0, a1, m);
        }
#undef PG_ROW

        // two-stage gbar merge: warps 4-7 store, warps 0-3 fold theirs in
        if (w >= 4) {
            ulonglong2 t0; t0.x = ga0; t0.y = ga1;
            ulonglong2 t1; t1.x = ga2; t1.y = ga3;
            *(ulonglong2*)(s_gb + (w - 4) * NDIM + n0) = t0;
            *(ulonglong2*)(s_gb + (w - 4) * NDIM + n1) = t1;
        }
        __syncthreads();
        if (w < 4) {
            ulonglong2 t0 = *(ulonglong2*)(s_gb + w * NDIM + n0);
            ulonglong2 t1 = *(ulonglong2*)(s_gb + w * NDIM + n1);
            t0.x = add2(ga0, t0.x); t0.y = add2(ga1, t0.y);
            t1.x = add2(ga2, t1.x); t1.y = add2(ga3, t1.y);
            *(ulonglong2*)(s_gb + w * NDIM + n0) = t0;
            *(ulonglong2*)(s_gb + w * NDIM + n1) = t1;
        }
        __syncthreads();

        // grad + column-constraint mask bits (per-thread, serial + fast path)
        if (tid < NDIM) {
            float gb = 0.f;
#pragma unroll
            for (int j = 0; j < 4; j++) gb += s_gb[j * NDIM + tid];
            const float xv  = s_x[tid];
            const float lov = s_lo[tid];
            const float slo = fmaxf(xv - lov, 1e-12f);
            const float gr  = (xv - s_xr[tid]) + gb + __fdividef(MUF, slo);
            s_grad[tid] = gr;

            const float lim = lov + EPSF;
            if (!(gr <= 0.f && xv >= lim)) {   // fast path: all candidates pass
                unsigned mk = MASK_ALL;
                float st = 1.f;
#pragma unroll
                for (int l = 0; l < LMAX; l++) {
                    const float c = fmaf(-st, gr, xv);
                    if (!(c >= lim)) mk &= ~(1u << l);
                    st *= 0.5f;
                }
                if (mk != MASK_ALL) atomicAnd(&s_mask, mk);
            }
        }
        __syncthreads();

        // ---- pass A: Ag dots (8-row batched butterfly) + ballot row masks ---
        const ulonglong2 gA = *(const ulonglong2*)(s_grad + n0);
        const ulonglong2 gB = *(const ulonglong2*)(s_grad + n1);
        unsigned wmask = MASK_ALL;
        const int rrow = ((lane >> 4) & 1) * 4 + ((lane >> 3) & 1) * 2
                       + ((lane >> 2) & 1);   // row index this lane's sum maps to

#define PA_DOT(A0, A1, dst)                                                   \
        do {                                                                  \
            u64 s_ = mul2((A0).x, gA.x);                                      \
            s_ = fma2((A0).y, gA.y, s_);                                      \
            s_ = fma2((A1).x, gB.x, s_);                                      \
            s_ = fma2((A1).y, gB.y, s_);                                      \
            float sl_, sh_; unpack2(s_, sl_, sh_);                            \
            dst = sl_ + sh_;                                                  \
        } while (0)

        {
            // batch 1: rows j = 8..15 (gmem)
            float prt[8];
#pragma unroll
            for (int i = 0; i < 8; i++) {
                const int m = w + 8 * (8 + i);
                const ulonglong2 a0 = *(const ulonglong2*)(Aw + (size_t)m * NDIM + n0);
                const ulonglong2 a1 = *(const ulonglong2*)(Aw + (size_t)m * NDIM + n1);
                PA_DOT(a0, a1, prt[i]);
            }
            const float S = mreduce8(prt, lane);
            if ((lane & 3) == 0) s_Ag[w + 8 * (8 + rrow)] = S;
#pragma unroll
            for (int i = 0; i < 8; i++) {
                const float ag = __shfl_sync(0xffffffffu, S, 4 * i);
                const int m = w + 8 * (8 + i);
                const float axc = fmaf(-stepl, ag, s_Ax[m]);
                const unsigned bits =
                    __ballot_sync(0xffffffffu, axc <= s_bw[m] - EPSF);
                wmask &= (bits | ~MASK_ALL);
            }
        }
        {
            // batch 2: rows j = 0..7 (pinned i<5; i==5 pinned iff w<4; else gmem)
            float prt[8];
#pragma unroll
            for (int i = 0; i < 8; i++) {
                const int m = w + 8 * i;
                const float* src =
                    (i < CJ) ? (sA + m * NDIM)
                  : ((i == 5) ? ((w < 4) ? (sA + m * NDIM)
                                         : (Aw + (size_t)m * NDIM))
                              : (Aw + (size_t)m * NDIM));
                const ulonglong2 a0 = *(const ulonglong2*)(src + n0);
                const ulonglong2 a1 = *(const ulonglong2*)(src + n1);
                PA_DOT(a0, a1, prt[i]);
            }
            const float S = mreduce8(prt, lane);
            if ((lane & 3) == 0) s_Ag[w + 8 * rrow] = S;
#pragma unroll
            for (int i = 0; i < 8; i++) {
                const float ag = __shfl_sync(0xffffffffu, S, 4 * i);
                const int m = w + 8 * i;
                const float axc = fmaf(-stepl, ag, s_Ax[m]);
                const unsigned bits =
                    __ballot_sync(0xffffffffu, axc <= s_bw[m] - EPSF);
                wmask &= (bits | ~MASK_ALL);
            }
        }
#undef PA_DOT

        if (lane == 0 && wmask != MASK_ALL) atomicAnd(&s_mask, wmask);

        // cross-barrier prefetch for NEXT iteration's pass G (row j = 6):
        // A is constant -> no dependency; L2 latency hides under the spin.
        pf0 = *(const ulonglong2*)(Aw + (size_t)(w + 48) * NDIM + n0);
        pf1 = *(const ulonglong2*)(Aw + (size_t)(w + 48) * NDIM + n1);

        __syncthreads();

        // ---- flat global barrier; release word carries the step -------------
        if (tid == 0) {
            atomicAnd(&g_and[k], s_mask);
            __threadfence();
            if (atomicAdd(&g_cnt[k], 1u) == NPROB - 1u) {   // last arrival
                __threadfence();
                const unsigned fin = *(volatile unsigned*)&g_and[k] & MASK_ALL;
                const unsigned sb = fin ? (unsigned)(__ffs(fin) - 1) : 0xFFu;
                atomicExch(&g_rel, ((unsigned)(k + 1) << 8) | sb);
            }
            unsigned relv;
            while (((relv = *(volatile unsigned*)&g_rel) >> 8) != (unsigned)(k + 1))
                __nanosleep(32);
            const unsigned sb = relv & 0xFFu;
            s_step = (sb == 0xFFu) ? 0.f
                                   : __uint_as_float((127u - sb) << 23);
            s_mask = MASK_ALL;                // reset for next iteration
        }
        __syncthreads();

        // EXACT early exit: step==0 leaves x unchanged, so every remaining
        // iteration recomputes identical masks and also accepts nothing.
        // The decision is uniform across all CTAs (same release word).
        if (s_step == 0.f) break;

        // owner-thread updates: x, Ax, and v for the next iteration
        if (tid < NDIM) s_x[tid] = fmaf(-s_step, s_grad[tid], s_x[tid]);
        if (tid < MDIM) {
            const float nAx = fmaf(-s_step, s_Ag[tid], s_Ax[tid]);
            s_Ax[tid] = nAx;
            s_v[tid]  = __fdividef(MUF, fmaxf(s_bw[tid] - nAx, 1e-12f));
        }
        __syncthreads();   // s_v/s_x/s_mask visible to all for next iteration
    }

    // finalize: relu(x) -> out
    if (tid < NDIM) out[p * NDIM + tid] = fmaxf(s_x[tid], 0.f);
}

extern "C" void kernel_launch(void* const* d_in, const int* in_sizes, int n_in,
                              void* d_out, int out_size) {
    // Identify inputs by size (dict order: x_raw, A, b, lower).
    int iA = 1, ib = 2, iv1 = 0, iv2 = 3;
    {
        int big = -1, small = -1, v1 = -1, v2 = -1;
        for (int i = 0; i < n_in; i++) {
            if (in_sizes[i] == NPROB * MDIM * NDIM) big = i;
            else if (in_sizes[i] == NPROB * MDIM)   small = i;
            else if (v1 < 0) v1 = i;
            else             v2 = i;
        }
        if (big >= 0 && small >= 0 && v1 >= 0 && v2 >= 0) {
            iA = big; ib = small; iv1 = v1; iv2 = v2;
        }
    }
    const float* xr  = (const float*)d_in[iv1];
    const float* A   = (const float*)d_in[iA];
    const float* b   = (const float*)d_in[ib];
    const float* low = (const float*)d_in[iv2];
    float* out = (float*)d_out;

    // Opt-in: static (~10.3KB) + dynamic (44KB) > 48KB default per-block limit.
    // Not a stream-ordered call -> does not enter / invalidate graph capture.
    cudaFuncSetAttribute(persist_kernel,
                         cudaFuncAttributeMaxDynamicSharedMemorySize, DYNSMEM);

    persist_kernel<<<NPROB, TPB, DYNSMEM>>>(xr, A, b, low, out);
}

// round 16
// speedup vs baseline: 3.7722x; 1.0245x over previous
#include <cuda_runtime.h>
#include <cstdint>

#define NPROB 512            // B*S = 32*16
#define MDIM  128
#define NDIM  256
#define EPSF  1e-6f
#define MUF   0.01f
#define KITER 30
#define LMAX  25
#define MASK_ALL 0x01FFFFFFu // 25 bits
#define TPB   256
#define CJ    5              // full pinned row-groups (rows 0..39)
#define CROWS 44             // rows 0..43 pinned (row 40+w pinned for warps 0..3)
#define DYNSMEM (CROWS * NDIM * 4)   // 45056 B

typedef unsigned long long u64;

// Persistent device state
__device__ float    g_Aw[(size_t)NPROB * MDIM * NDIM]; // row-normalized A (64MB)
__device__ unsigned g_count;                            // setup barrier counter
__device__ unsigned g_sense;                            // setup barrier sense
__device__ unsigned g_and[KITER];                       // per-iter AND of masks
__device__ unsigned g_cnt[KITER];                       // per-iter arrival count
__device__ unsigned g_rel;                              // release: (epoch<<8)|stepbyte

// ---- packed f32x2 helpers (sm_103a FFMA2 path; per-element IEEE fp32) ----
__device__ __forceinline__ u64 pack2(float x, float y) {
    u64 r; asm("mov.b64 %0, {%1, %2};" : "=l"(r) : "f"(x), "f"(y)); return r;
}
__device__ __forceinline__ void unpack2(u64 v, float& x, float& y) {
    asm("mov.b64 {%0, %1}, %2;" : "=f"(x), "=f"(y) : "l"(v));
}
__device__ __forceinline__ u64 fma2(u64 a, u64 b, u64 c) {
    u64 d; asm("fma.rn.f32x2 %0, %1, %2, %3;" : "=l"(d) : "l"(a), "l"(b), "l"(c));
    return d;
}
__device__ __forceinline__ u64 mul2(u64 a, u64 b) {
    u64 d; asm("mul.rn.f32x2 %0, %1, %2;" : "=l"(d) : "l"(a), "l"(b));
    return d;
}
__device__ __forceinline__ u64 add2(u64 a, u64 b) {
    u64 d; asm("add.rn.f32x2 %0, %1, %2;" : "=l"(d) : "l"(a), "l"(b));
    return d;
}

// NOTE: redux.sync.add.f32 is NOT supported on sm_103 (ptxas rejects it).
__device__ __forceinline__ float warp_allreduce_add(float v) {
#pragma unroll
    for (int o = 16; o; o >>= 1) v += __shfl_xor_sync(0xffffffffu, v, o);
    return v;
}

// Multi-row reduction: 8 independent 32-lane sums in 9 shfls.
// Row i's sum follows the SAME xor-16,8,4,2,1 pairing tree as
// warp_allreduce_add -> bit-identical results. Row i's sum lives
// (replicated) in lanes 4i..4i+3.
__device__ __forceinline__ float mreduce8(const float V[8], int lane) {
    const bool lo16 = (lane & 16) == 0;
    float W[4];
#pragma unroll
    for (int i = 0; i < 4; i++) {
        const float send = lo16 ? V[i + 4] : V[i];
        const float keep = lo16 ? V[i]     : V[i + 4];
        W[i] = keep + __shfl_xor_sync(0xffffffffu, send, 16);
    }
    const bool lo8 = (lane & 8) == 0;
    float X[2];
#pragma unroll
    for (int i = 0; i < 2; i++) {
        const float send = lo8 ? W[i + 2] : W[i];
        const float keep = lo8 ? W[i]     : W[i + 2];
        X[i] = keep + __shfl_xor_sync(0xffffffffu, send, 8);
    }
    const bool lo4 = (lane & 4) == 0;
    {
        const float send = lo4 ? X[1] : X[0];
        const float keep = lo4 ? X[0] : X[1];
        float Y = keep + __shfl_xor_sync(0xffffffffu, send, 4);
        Y += __shfl_xor_sync(0xffffffffu, Y, 2);
        Y += __shfl_xor_sync(0xffffffffu, Y, 1);
        return Y;
    }
}

__device__ __forceinline__ float dot8(float4 a0, float4 a1, float4 b0, float4 b1) {
    float s = a0.x * b0.x + a0.y * b0.y + a0.z * b0.z + a0.w * b0.w;
    s += a1.x * b1.x + a1.y * b1.y + a1.z * b1.z + a1.w * b1.w;
    return s;
}

// Setup-only grid barrier (runs once). All NPROB CTAs co-resident:
// __launch_bounds__(256,4) + ~54KB smem/CTA -> 4 CTAs/SM * 148 = 592 >= 512.
#define GRID_BARRIER()                                                        \
    do {                                                                      \
        __syncthreads();                                                      \
        if (tid == 0) {                                                       \
            const unsigned target = sense ^ 1u;                               \
            __threadfence();                                                  \
            if (atomicAdd(&g_count, 1u) == NPROB - 1u) {                      \
                atomicExch(&g_count, 0u);                                     \
                __threadfence();                                              \
                atomicExch(&g_sense, target);                                 \
            } else {                                                          \
                while (*(volatile unsigned*)&g_sense != target)               \
                    __nanosleep(64);                                          \
            }                                                                 \
            sense = target;                                                   \
            __threadfence();                                                  \
        }                                                                     \
        __syncthreads();                                                      \
    } while (0)

__global__ void __launch_bounds__(TPB, 4)
persist_kernel(const float* __restrict__ xraw,
               const float* __restrict__ Ain,
               const float* __restrict__ bin,
               const float* __restrict__ lowin,
               float* __restrict__ out)
{
    extern __shared__ __align__(16) float sA[];   // CROWS x NDIM pinned A rows

    const int p    = blockIdx.x;
    const int tid  = threadIdx.x;
    const int lane = tid & 31;
    const int w    = tid >> 5;

    __shared__ __align__(16) float s_x[NDIM];
    __shared__ __align__(16) float s_grad[NDIM];
    __shared__ __align__(16) float s_lo[NDIM];
    __shared__ __align__(16) float s_xr[NDIM];
    __shared__ __align__(16) float s_bw[MDIM];
    __shared__ __align__(16) float s_Ax[MDIM];
    __shared__ __align__(16) float s_Ag[MDIM];
    __shared__ __align__(16) float s_v[MDIM];
    __shared__ __align__(16) float s_gb[4 * NDIM];   // merged gbar partials (4KB)
    __shared__ unsigned s_mask;
    __shared__ float    s_step;
    __shared__ int      s_feas;

    const float* A  = Ain  + (size_t)p * MDIM * NDIM;
    float*       Aw = g_Aw + (size_t)p * MDIM * NDIM;

    // Read sense BEFORE first arrive (all CTAs read pre-flip value).
    unsigned sense = *(volatile unsigned*)&g_sense;

    if (p == 0) {
        if (tid < KITER) { g_and[tid] = MASK_ALL; g_cnt[tid] = 0u; }
        if (tid == 0)    g_rel = 0u;   // stale epochs can never match 1..KITER
    }

    if (tid < NDIM) {
        s_lo[tid] = lowin[p * NDIM + tid];
        s_xr[tid] = xraw[p * NDIM + tid];
    }
    if (tid == 0) s_feas = 1;
    __syncthreads();

    const int n0 = 4 * lane;
    const int n1 = 128 + 4 * lane;
    const float4 l0 = *(const float4*)(s_lo + n0);
    const float4 l1 = *(const float4*)(s_lo + n1);

    // per-lane line-search step: lane l tests step 2^-l (exact power of two)
    const float stepl = __uint_as_float((unsigned)(127 - lane) << 23);

    float* s_red = s_gb;   // alias: s_gb unused during setup (>= MDIM floats)

    // ------- setup: ONE pass over A. Normalize, pin rows 0..43 in smem,
    // store only rows >= CROWS to gmem (pinned rows never read from gmem).
    // Stash ad = Aw@1 in s_Ax, sd = Aw@lower in s_Ag, ratio in s_red. -------
#pragma unroll 4
    for (int j = 0; j < 16; j++) {
        const int m = w + 8 * j;
        const float4 a0 = *(const float4*)(A + (size_t)m * NDIM + n0);
        const float4 a1 = *(const float4*)(A + (size_t)m * NDIM + n1);
        float ss = warp_allreduce_add(dot8(a0, a1, a0, a1));
        const float norm = fmaxf(sqrtf(ss), 1e-12f);
        float4 w0, w1;
        w0.x = a0.x / norm; w0.y = a0.y / norm; w0.z = a0.z / norm; w0.w = a0.w / norm;
        w1.x = a1.x / norm; w1.y = a1.y / norm; w1.z = a1.z / norm; w1.w = a1.w / norm;
        if (m < CROWS) {
            *(float4*)(sA + m * NDIM + n0) = w0;
            *(float4*)(sA + m * NDIM + n1) = w1;
        } else {
            *(float4*)(Aw + (size_t)m * NDIM + n0) = w0;
            *(float4*)(Aw + (size_t)m * NDIM + n1) = w1;
        }
        float ad = (w0.x + w0.y + w0.z + w0.w) + (w1.x + w1.y + w1.z + w1.w);
        float sd = dot8(w0, w1, l0, l1);
        ad = warp_allreduce_add(ad);
        sd = warp_allreduce_add(sd);
        if (lane == 0) {
            const float bwm = bin[p * MDIM + m] / norm;
            s_bw[m]  = bwm;
            s_Ax[m]  = ad;          // Ad = Aw @ 1
            s_Ag[m]  = sd;          // Aw @ lower
            s_red[m] = (ad > 0.f) ? (bwm - sd) / fmaxf(ad, 1e-12f)
                                  : __int_as_float(0x7f800000); // +inf
        }
    }
    __syncthreads();

    // t = max(0.5 * min_m ratio, 2*eps)
    for (int off = 64; off >= 1; off >>= 1) {
        if (tid < off) s_red[tid] = fminf(s_red[tid], s_red[tid + off]);
        __syncthreads();
    }
    const float t = fmaxf(0.5f * s_red[0], 2.f * EPSF);
    __syncthreads();   // s_red (=s_gb) free again

    // Closed-form Ax seed + feasibility on x0 = lower + t:
    //   Ax0[m] = sd[m] + t*ad[m]  (algebraically exact; ~1e-7 rounding vs
    //   fresh dot, decision margins here are O(0.05) >> eps)
    if (tid < MDIM) {
        const float ax0 = fmaf(t, s_Ax[tid], s_Ag[tid]);
        s_Ax[tid] = ax0;
        if (!(ax0 <= s_bw[tid] - EPSF)) atomicAnd(&s_feas, 0);
    }
    if (tid < NDIM) {
        const float xv = s_lo[tid] + t;
        if (!(xv >= s_lo[tid] + EPSF)) atomicAnd(&s_feas, 0);
    }
    __syncthreads();
    if (tid < NDIM) {
        float xv = s_lo[tid] + t;
        if (!s_feas) xv = 0.5f * (fmaxf(xv, 0.f) + s_lo[tid]);
        s_x[tid] = xv;
    }
    __syncthreads();
    if (!s_feas) {   // rare repair branch: recompute Ax of repaired x (fresh)
        const float4 r0 = *(const float4*)(s_x + n0);
        const float4 r1 = *(const float4*)(s_x + n1);
        for (int j = 0; j < 16; j++) {
            const int m = w + 8 * j;
            const float* src = (m < CROWS) ? (sA + m * NDIM)
                                           : (Aw + (size_t)m * NDIM);
            const float4 a0 = *(const float4*)(src + n0);
            const float4 a1 = *(const float4*)(src + n1);
            float d = warp_allreduce_add(dot8(a0, a1, r0, r1));
            if (lane == 0) s_Ax[m] = d;
        }
    }

    GRID_BARRIER();   // barrier #0: barrier-state init + everyone's setup done

    // prime v and s_mask for iteration 0
    if (tid < MDIM)
        s_v[tid] = __fdividef(MUF, fmaxf(s_bw[tid] - s_Ax[tid], 1e-12f));
    if (tid == 0) s_mask = MASK_ALL;
    __syncthreads();

    // prime cross-barrier prefetch: pass G's first all-warp gmem row (j = 6)
    ulonglong2 pf0 = *(const ulonglong2*)(Aw + (size_t)(w + 48) * NDIM + n0);
    ulonglong2 pf1 = *(const ulonglong2*)(Aw + (size_t)(w + 48) * NDIM + n1);

    // ---------------- main loop (incremental Ax: Ax_{k+1} = Ax_k - step*Ag) --
    for (int k = 0; k < KITER; k++) {
        // ---- pass G: gbar partials (pure streaming, no reduce/div) ---------
        u64 ga0 = 0ull, ga1 = 0ull, ga2 = 0ull, ga3 = 0ull;

#define PG_ROW(A0, A1, m)                                                     \
        do {                                                                  \
            const float v_ = s_v[m];                                          \
            const u64 vv = pack2(v_, v_);                                     \
            ga0 = fma2((A0).x, vv, ga0); ga1 = fma2((A0).y, vv, ga1);         \
            ga2 = fma2((A1).x, vv, ga2); ga3 = fma2((A1).y, vv, ga3);         \
        } while (0)

        // j = 6 from the cross-barrier prefetch (L2 latency hidden by spin)
        PG_ROW(pf0, pf1, w + 48);
        // j = 5: pinned for warps 0-3, gmem for warps 4-7 (uniform select)
        {
            const int m5 = w + 40;
            const float* s5 = (w < 4) ? (sA + m5 * NDIM)
                                      : (Aw + (size_t)m5 * NDIM);
            const ulonglong2 a0 = *(const ulonglong2*)(s5 + n0);
            const ulonglong2 a1 = *(const ulonglong2*)(s5 + n1);
            PG_ROW(a0, a1, m5);
        }
        // gmem rows j = 7 .. 15
#pragma unroll 4
        for (int j = 7; j < 16; j++) {
            const int m = w + 8 * j;
            const ulonglong2 a0 = *(const ulonglong2*)(Aw + (size_t)m * NDIM + n0);
            const ulonglong2 a1 = *(const ulonglong2*)(Aw + (size_t)m * NDIM + n1);
            PG_ROW(a0, a1, m);
        }
        // fully-pinned rows j = 0..4
#pragma unroll
        for (int j = 0; j < CJ; j++) {
            const int m = w + 8 * j;
            const ulonglong2 a0 = *(const ulonglong2*)(sA + m * NDIM + n0);
            const ulonglong2 a1 = *(const ulonglong2*)(sA + m * NDIM + n1);
            PG_ROW(a0, a1, m);
        }
#undef PG_ROW

        // two-stage gbar merge: warps 4-7 store, warps 0-3 fold theirs in
        if (w >= 4) {
            ulonglong2 t0; t0.x = ga0; t0.y = ga1;
            ulonglong2 t1; t1.x = ga2; t1.y = ga3;
            *(ulonglong2*)(s_gb + (w - 4) * NDIM + n0) = t0;
            *(ulonglong2*)(s_gb + (w - 4) * NDIM + n1) = t1;
        }
        __syncthreads();
        if (w < 4) {
            ulonglong2 t0 = *(ulonglong2*)(s_gb + w * NDIM + n0);
            ulonglong2 t1 = *(ulonglong2*)(s_gb + w * NDIM + n1);
            t0.x = add2(ga0, t0.x); t0.y = add2(ga1, t0.y);
            t1.x = add2(ga2, t1.x); t1.y = add2(ga3, t1.y);
            *(ulonglong2*)(s_gb + w * NDIM + n0) = t0;
            *(ulonglong2*)(s_gb + w * NDIM + n1) = t1;
        }
        __syncthreads();

        // grad + column-constraint mask bits (per-thread, serial + fast path)
        if (tid < NDIM) {
            float gb = 0.f;
#pragma unroll
            for (int j = 0; j < 4; j++) gb += s_gb[j * NDIM + tid];
            const float xv  = s_x[tid];
            const float lov = s_lo[tid];
            const float slo = fmaxf(xv - lov, 1e-12f);
            const float gr  = (xv - s_xr[tid]) + gb + __fdividef(MUF, slo);
            s_grad[tid] = gr;

            const float lim = lov + EPSF;
            if (!(gr <= 0.f && xv >= lim)) {   // fast path: all candidates pass
                unsigned mk = MASK_ALL;
                float st = 1.f;
#pragma unroll
                for (int l = 0; l < LMAX; l++) {
                    const float c = fmaf(-st, gr, xv);
                    if (!(c >= lim)) mk &= ~(1u << l);
                    st *= 0.5f;
                }
                if (mk != MASK_ALL) atomicAnd(&s_mask, mk);
            }
        }
        __syncthreads();

        // ---- pass A: Ag dots (8-row batched butterfly) + ballot row masks ---
        const ulonglong2 gA = *(const ulonglong2*)(s_grad + n0);
        const ulonglong2 gB = *(const ulonglong2*)(s_grad + n1);
        unsigned wmask = MASK_ALL;
        const int rrow = ((lane >> 4) & 1) * 4 + ((lane >> 3) & 1) * 2
                       + ((lane >> 2) & 1);   // row index this lane's sum maps to

#define PA_DOT(A0, A1, dst)                                                   \
        do {                                                                  \
            u64 s_ = mul2((A0).x, gA.x);                                      \
            s_ = fma2((A0).y, gA.y, s_);                                      \
            s_ = fma2((A1).x, gB.x, s_);                                      \
            s_ = fma2((A1).y, gB.y, s_);                                      \
            float sl_, sh_; unpack2(s_, sl_, sh_);                            \
            dst = sl_ + sh_;                                                  \
        } while (0)

        {
            // batch 1: rows j = 8..15 (gmem)
            float prt[8];
#pragma unroll
            for (int i = 0; i < 8; i++) {
                const int m = w + 8 * (8 + i);
                const ulonglong2 a0 = *(const ulonglong2*)(Aw + (size_t)m * NDIM + n0);
                const ulonglong2 a1 = *(const ulonglong2*)(Aw + (size_t)m * NDIM + n1);
                PA_DOT(a0, a1, prt[i]);
            }
            const float S = mreduce8(prt, lane);
            if ((lane & 3) == 0) s_Ag[w + 8 * (8 + rrow)] = S;
#pragma unroll
            for (int i = 0; i < 8; i++) {
                const float ag = __shfl_sync(0xffffffffu, S, 4 * i);
                const int m = w + 8 * (8 + i);
                const float axc = fmaf(-stepl, ag, s_Ax[m]);
                const unsigned bits =
                    __ballot_sync(0xffffffffu, axc <= s_bw[m] - EPSF);
                wmask &= (bits | ~MASK_ALL);
            }
        }
        {
            // batch 2: rows j = 0..7 (pinned i<5; i==5 pinned iff w<4; else gmem)
            float prt[8];
#pragma unroll
            for (int i = 0; i < 8; i++) {
                const int m = w + 8 * i;
                const float* src =
                    (i < CJ) ? (sA + m * NDIM)
                  : ((i == 5) ? ((w < 4) ? (sA + m * NDIM)
                                         : (Aw + (size_t)m * NDIM))
                              : (Aw + (size_t)m * NDIM));
                const ulonglong2 a0 = *(const ulonglong2*)(src + n0);
                const ulonglong2 a1 = *(const ulonglong2*)(src + n1);
                PA_DOT(a0, a1, prt[i]);
            }
            const float S = mreduce8(prt, lane);
            if ((lane & 3) == 0) s_Ag[w + 8 * rrow] = S;
#pragma unroll
            for (int i = 0; i < 8; i++) {
                const float ag = __shfl_sync(0xffffffffu, S, 4 * i);
                const int m = w + 8 * i;
                const float axc = fmaf(-stepl, ag, s_Ax[m]);
                const unsigned bits =
                    __ballot_sync(0xffffffffu, axc <= s_bw[m] - EPSF);
                wmask &= (bits | ~MASK_ALL);
            }
        }
#undef PA_DOT

        if (lane == 0 && wmask != MASK_ALL) atomicAnd(&s_mask, wmask);

        // cross-barrier prefetch for NEXT iteration's pass G (row j = 6):
        // A is constant -> no dependency; L2 latency hides under the spin.
        pf0 = *(const ulonglong2*)(Aw + (size_t)(w + 48) * NDIM + n0);
        pf1 = *(const ulonglong2*)(Aw + (size_t)(w + 48) * NDIM + n1);

        __syncthreads();

        // ---- flat global barrier; release word carries the step -------------
        if (tid == 0) {
            atomicAnd(&g_and[k], s_mask);
            __threadfence();
            if (atomicAdd(&g_cnt[k], 1u) == NPROB - 1u) {   // last arrival
                __threadfence();
                const unsigned fin = *(volatile unsigned*)&g_and[k] & MASK_ALL;
                const unsigned sb = fin ? (unsigned)(__ffs(fin) - 1) : 0xFFu;
                atomicExch(&g_rel, ((unsigned)(k + 1) << 8) | sb);
            }
            unsigned relv;
            while (((relv = *(volatile unsigned*)&g_rel) >> 8) != (unsigned)(k + 1))
                __nanosleep(32);
            const unsigned sb = relv & 0xFFu;
            s_step = (sb == 0xFFu) ? 0.f
                                   : __uint_as_float((127u - sb) << 23);
            s_mask = MASK_ALL;                // reset for next iteration
        }
        __syncthreads();

        // EXACT early exit: step==0 leaves x unchanged, so every remaining
        // iteration recomputes identical masks and also accepts nothing.
        // The decision is uniform across all CTAs (same release word).
        if (s_step == 0.f) break;

        // owner-thread updates: x, Ax, and v for the next iteration
        if (tid < NDIM) s_x[tid] = fmaf(-s_step, s_grad[tid], s_x[tid]);
        if (tid < MDIM) {
            const float nAx = fmaf(-s_step, s_Ag[tid], s_Ax[tid]);
            s_Ax[tid] = nAx;
            s_v[tid]  = __fdividef(MUF, fmaxf(s_bw[tid] - nAx, 1e-12f));
        }
        __syncthreads();   // s_v/s_x/s_mask visible to all for next iteration
    }

    // finalize: relu(x) -> out
    if (tid < NDIM) out[p * NDIM + tid] = fmaxf(s_x[tid], 0.f);
}

extern "C" void kernel_launch(void* const* d_in, const int* in_sizes, int n_in,
                              void* d_out, int out_size) {
    // Identify inputs by size (dict order: x_raw, A, b, lower).
    int iA = 1, ib = 2, iv1 = 0, iv2 = 3;
    {
        int big = -1, small = -1, v1 = -1, v2 = -1;
        for (int i = 0; i < n_in; i++) {
            if (in_sizes[i] == NPROB * MDIM * NDIM) big = i;
            else if (in_sizes[i] == NPROB * MDIM)   small = i;
            else if (v1 < 0) v1 = i;
            else             v2 = i;
        }
        if (big >= 0 && small >= 0 && v1 >= 0 && v2 >= 0) {
            iA = big; ib = small; iv1 = v1; iv2 = v2;
        }
    }
    const float* xr  = (const float*)d_in[iv1];
    const float* A   = (const float*)d_in[iA];
    const float* b   = (const float*)d_in[ib];
    const float* low = (const float*)d_in[iv2];
    float* out = (float*)d_out;

    // Opt-in: static (~10.3KB) + dynamic (44KB) > 48KB default per-block limit.
    // Not a stream-ordered call -> does not enter / invalidate graph capture.
    cudaFuncSetAttribute(persist_kernel,
                         cudaFuncAttributeMaxDynamicSharedMemorySize, DYNSMEM);

    persist_kernel<<<NPROB, TPB, DYNSMEM>>>(xr, A, b, low, out);
}

// round 17
// speedup vs baseline: 4.1710x; 1.1057x over previous
#include <cuda_runtime.h>
#include <cstdint>

#define NPROB 512            // B*S = 32*16
#define MDIM  128
#define NDIM  256
#define EPSF  1e-6f
#define MUF   0.01f
#define KITER 30
#define LMAX  25
#define MASK_ALL 0x01FFFFFFu // 25 bits
#define TPB   256
#define CJ    5              // full pinned row-groups (rows 0..39)
#define CROWS 44             // rows 0..43 pinned (row 40+w pinned for warps 0..3)
#define DYNSMEM (CROWS * NDIM * 4)   // 45056 B

typedef unsigned long long u64;

// Persistent device state (NOTE: no normalized-A copy any more — the loop
// streams RAW A and folds 1/norm into v and Ag scalars)
__device__ unsigned g_count;                            // setup barrier counter
__device__ unsigned g_sense;                            // setup barrier sense
__device__ unsigned g_and[KITER];                       // per-iter AND of masks
__device__ unsigned g_cnt[KITER];                       // per-iter arrival count
__device__ unsigned g_rel;                              // release: (epoch<<8)|stepbyte

// ---- packed f32x2 helpers (sm_103a FFMA2 path; per-element IEEE fp32) ----
__device__ __forceinline__ u64 pack2(float x, float y) {
    u64 r; asm("mov.b64 %0, {%1, %2};" : "=l"(r) : "f"(x), "f"(y)); return r;
}
__device__ __forceinline__ void unpack2(u64 v, float& x, float& y) {
    asm("mov.b64 {%0, %1}, %2;" : "=f"(x), "=f"(y) : "l"(v));
}
__device__ __forceinline__ u64 fma2(u64 a, u64 b, u64 c) {
    u64 d; asm("fma.rn.f32x2 %0, %1, %2, %3;" : "=l"(d) : "l"(a), "l"(b), "l"(c));
    return d;
}
__device__ __forceinline__ u64 mul2(u64 a, u64 b) {
    u64 d; asm("mul.rn.f32x2 %0, %1, %2;" : "=l"(d) : "l"(a), "l"(b));
    return d;
}
__device__ __forceinline__ u64 add2(u64 a, u64 b) {
    u64 d; asm("add.rn.f32x2 %0, %1, %2;" : "=l"(d) : "l"(a), "l"(b));
    return d;
}

// NOTE: redux.sync.add.f32 is NOT supported on sm_103 (ptxas rejects it).
__device__ __forceinline__ float warp_allreduce_add(float v) {
#pragma unroll
    for (int o = 16; o; o >>= 1) v += __shfl_xor_sync(0xffffffffu, v, o);
    return v;
}

// Multi-row reduction: 8 independent 32-lane sums in 9 shfls.
// Row i's sum follows the SAME xor-16,8,4,2,1 pairing tree as
// warp_allreduce_add -> bit-identical results. Row i's sum lives
// (replicated) in lanes 4i..4i+3.
__device__ __forceinline__ float mreduce8(const float V[8], int lane) {
    const bool lo16 = (lane & 16) == 0;
    float W[4];
#pragma unroll
    for (int i = 0; i < 4; i++) {
        const float send = lo16 ? V[i + 4] : V[i];
        const float keep = lo16 ? V[i]     : V[i + 4];
        W[i] = keep + __shfl_xor_sync(0xffffffffu, send, 16);
    }
    const bool lo8 = (lane & 8) == 0;
    float X[2];
#pragma unroll
    for (int i = 0; i < 2; i++) {
        const float send = lo8 ? W[i + 2] : W[i];
        const float keep = lo8 ? W[i]     : W[i + 2];
        X[i] = keep + __shfl_xor_sync(0xffffffffu, send, 8);
    }
    const bool lo4 = (lane & 4) == 0;
    {
        const float send = lo4 ? X[1] : X[0];
        const float keep = lo4 ? X[0] : X[1];
        float Y = keep + __shfl_xor_sync(0xffffffffu, send, 4);
        Y += __shfl_xor_sync(0xffffffffu, Y, 2);
        Y += __shfl_xor_sync(0xffffffffu, Y, 1);
        return Y;
    }
}

__device__ __forceinline__ float dot8(float4 a0, float4 a1, float4 b0, float4 b1) {
    float s = a0.x * b0.x + a0.y * b0.y + a0.z * b0.z + a0.w * b0.w;
    s += a1.x * b1.x + a1.y * b1.y + a1.z * b1.z + a1.w * b1.w;
    return s;
}

// Setup-only grid barrier (runs once). All NPROB CTAs co-resident:
// __launch_bounds__(256,4) + ~55KB smem/CTA -> 4 CTAs/SM * 148 = 592 >= 512.
#define GRID_BARRIER()                                                        \
    do {                                                                      \
        __syncthreads();                                                      \
        if (tid == 0) {                                                       \
            const unsigned target = sense ^ 1u;                               \
            __threadfence();                                                  \
            if (atomicAdd(&g_count, 1u) == NPROB - 1u) {                      \
                atomicExch(&g_count, 0u);                                     \
                __threadfence();                                              \
                atomicExch(&g_sense, target);                                 \
            } else {                                                          \
                while (*(volatile unsigned*)&g_sense != target)               \
                    __nanosleep(64);                                          \
            }                                                                 \
            sense = target;                                                   \
            __threadfence();                                                  \
        }                                                                     \
        __syncthreads();                                                      \
    } while (0)

__global__ void __launch_bounds__(TPB, 4)
persist_kernel(const float* __restrict__ xraw,
               const float* __restrict__ Ain,
               const float* __restrict__ bin,
               const float* __restrict__ lowin,
               float* __restrict__ out)
{
    extern __shared__ __align__(16) float sA[];   // CROWS x NDIM RAW A rows

    const int p    = blockIdx.x;
    const int tid  = threadIdx.x;
    const int lane = tid & 31;
    const int w    = tid >> 5;

    __shared__ __align__(16) float s_x[NDIM];
    __shared__ __align__(16) float s_grad[NDIM];
    __shared__ __align__(16) float s_lo[NDIM];
    __shared__ __align__(16) float s_xr[NDIM];
    __shared__ __align__(16) float s_bw[MDIM];
    __shared__ __align__(16) float s_Ax[MDIM];
    __shared__ __align__(16) float s_Ag[MDIM];
    __shared__ __align__(16) float s_v[MDIM];     // v' = mu/slack * inorm
    __shared__ __align__(16) float s_in[MDIM];    // 1/row_norm
    __shared__ __align__(16) float s_gb[4 * NDIM];   // merged gbar partials (4KB)
    __shared__ unsigned s_mask;
    __shared__ float    s_step;
    __shared__ int      s_feas;

    const float* A = Ain + (size_t)p * MDIM * NDIM;

    // Read sense BEFORE first arrive (all CTAs read pre-flip value).
    unsigned sense = *(volatile unsigned*)&g_sense;

    if (p == 0) {
        if (tid < KITER) { g_and[tid] = MASK_ALL; g_cnt[tid] = 0u; }
        if (tid == 0)    g_rel = 0u;   // stale epochs can never match 1..KITER
    }

    if (tid < NDIM) {
        s_lo[tid] = lowin[p * NDIM + tid];
        s_xr[tid] = xraw[p * NDIM + tid];
    }
    if (tid == 0) s_feas = 1;
    __syncthreads();

    const int n0 = 4 * lane;
    const int n1 = 128 + 4 * lane;
    const float4 l0 = *(const float4*)(s_lo + n0);
    const float4 l1 = *(const float4*)(s_lo + n1);

    // per-lane line-search step: lane l tests step 2^-l (exact power of two)
    const float stepl = __uint_as_float((unsigned)(127 - lane) << 23);

    float* s_red = s_gb;   // alias: s_gb unused during setup (>= MDIM floats)

    // ------- setup: ONE pass over RAW A. Compute norms, pin rows 0..43
    // (raw values), NO gmem writes. Stash ad = A@1, sd = A@lower (raw),
    // then scale by inorm. -----------------------------------------------
#pragma unroll 4
    for (int j = 0; j < 16; j++) {
        const int m = w + 8 * j;
        const float4 a0 = *(const float4*)(A + (size_t)m * NDIM + n0);
        const float4 a1 = *(const float4*)(A + (size_t)m * NDIM + n1);
        float ss = warp_allreduce_add(dot8(a0, a1, a0, a1));
        const float norm  = fmaxf(sqrtf(ss), 1e-12f);
        const float inorm = 1.0f / norm;
        if (m < CROWS) {
            *(float4*)(sA + m * NDIM + n0) = a0;
            *(float4*)(sA + m * NDIM + n1) = a1;
        }
        float ad = (a0.x + a0.y + a0.z + a0.w) + (a1.x + a1.y + a1.z + a1.w);
        float sd = dot8(a0, a1, l0, l1);
        ad = warp_allreduce_add(ad);
        sd = warp_allreduce_add(sd);
        if (lane == 0) {
            const float bwm = bin[p * MDIM + m] / norm;
            const float adn = ad * inorm;
            const float sdn = sd * inorm;
            s_bw[m]  = bwm;
            s_in[m]  = inorm;
            s_Ax[m]  = adn;          // Ad = Aw @ 1
            s_Ag[m]  = sdn;          // Aw @ lower
            s_red[m] = (adn > 0.f) ? (bwm - sdn) / fmaxf(adn, 1e-12f)
                                   : __int_as_float(0x7f800000); // +inf
        }
    }
    __syncthreads();

    // t = max(0.5 * min_m ratio, 2*eps)
    for (int off = 64; off >= 1; off >>= 1) {
        if (tid < off) s_red[tid] = fminf(s_red[tid], s_red[tid + off]);
        __syncthreads();
    }
    const float t = fmaxf(0.5f * s_red[0], 2.f * EPSF);
    __syncthreads();   // s_red (=s_gb) free again

    // Closed-form Ax seed + feasibility on x0 = lower + t:
    //   Ax0[m] = sd[m] + t*ad[m]  (algebraically exact; decision margins
    //   here are O(0.05) >> eps)
    if (tid < MDIM) {
        const float ax0 = fmaf(t, s_Ax[tid], s_Ag[tid]);
        s_Ax[tid] = ax0;
        if (!(ax0 <= s_bw[tid] - EPSF)) atomicAnd(&s_feas, 0);
    }
    if (tid < NDIM) {
        const float xv = s_lo[tid] + t;
        if (!(xv >= s_lo[tid] + EPSF)) atomicAnd(&s_feas, 0);
    }
    __syncthreads();
    if (tid < NDIM) {
        float xv = s_lo[tid] + t;
        if (!s_feas) xv = 0.5f * (fmaxf(xv, 0.f) + s_lo[tid]);
        s_x[tid] = xv;
    }
    __syncthreads();
    if (!s_feas) {   // rare repair branch: recompute Ax of repaired x (raw dot * inorm)
        const float4 r0 = *(const float4*)(s_x + n0);
        const float4 r1 = *(const float4*)(s_x + n1);
        for (int j = 0; j < 16; j++) {
            const int m = w + 8 * j;
            const float* src = (m < CROWS) ? (sA + m * NDIM)
                                           : (A + (size_t)m * NDIM);
            const float4 a0 = *(const float4*)(src + n0);
            const float4 a1 = *(const float4*)(src + n1);
            float d = warp_allreduce_add(dot8(a0, a1, r0, r1));
            if (lane == 0) s_Ax[m] = d * s_in[m];
        }
    }

    GRID_BARRIER();   // barrier #0: barrier-state init + everyone's setup done

    // prime v' = mu/slack * inorm and s_mask for iteration 0
    if (tid < MDIM)
        s_v[tid] = __fdividef(MUF, fmaxf(s_bw[tid] - s_Ax[tid], 1e-12f)) * s_in[tid];
    if (tid == 0) s_mask = MASK_ALL;
    __syncthreads();

    // prime cross-barrier prefetch: pass G's first all-warp gmem row (j = 6)
    ulonglong2 pf0 = *(const ulonglong2*)(A + (size_t)(w + 48) * NDIM + n0);
    ulonglong2 pf1 = *(const ulonglong2*)(A + (size_t)(w + 48) * NDIM + n1);

    // ---------------- main loop (incremental Ax: Ax_{k+1} = Ax_k - step*Ag) --
    for (int k = 0; k < KITER; k++) {
        // ---- pass G: gbar partials over RAW A with v' (no reduce/div) ------
        u64 ga0 = 0ull, ga1 = 0ull, ga2 = 0ull, ga3 = 0ull;

#define PG_ROW(A0, A1, m)                                                     \
        do {                                                                  \
            const float v_ = s_v[m];                                          \
            const u64 vv = pack2(v_, v_);                                     \
            ga0 = fma2((A0).x, vv, ga0); ga1 = fma2((A0).y, vv, ga1);         \
            ga2 = fma2((A1).x, vv, ga2); ga3 = fma2((A1).y, vv, ga3);         \
        } while (0)

        // j = 6 from the cross-barrier prefetch (L2 latency hidden by spin)
        PG_ROW(pf0, pf1, w + 48);
        // j = 5: pinned for warps 0-3, gmem for warps 4-7 (uniform select)
        {
            const int m5 = w + 40;
            const float* s5 = (w < 4) ? (sA + m5 * NDIM)
                                      : (A + (size_t)m5 * NDIM);
            const ulonglong2 a0 = *(const ulonglong2*)(s5 + n0);
            const ulonglong2 a1 = *(const ulonglong2*)(s5 + n1);
            PG_ROW(a0, a1, m5);
        }
        // gmem rows j = 7 .. 15
#pragma unroll 4
        for (int j = 7; j < 16; j++) {
            const int m = w + 8 * j;
            const ulonglong2 a0 = *(const ulonglong2*)(A + (size_t)m * NDIM + n0);
            const ulonglong2 a1 = *(const ulonglong2*)(A + (size_t)m * NDIM + n1);
            PG_ROW(a0, a1, m);
        }
        // fully-pinned rows j = 0..4
#pragma unroll
        for (int j = 0; j < CJ; j++) {
            const int m = w + 8 * j;
            const ulonglong2 a0 = *(const ulonglong2*)(sA + m * NDIM + n0);
            const ulonglong2 a1 = *(const ulonglong2*)(sA + m * NDIM + n1);
            PG_ROW(a0, a1, m);
        }
#undef PG_ROW

        // two-stage gbar merge: warps 4-7 store, warps 0-3 fold theirs in
        if (w >= 4) {
            ulonglong2 t0; t0.x = ga0; t0.y = ga1;
            ulonglong2 t1; t1.x = ga2; t1.y = ga3;
            *(ulonglong2*)(s_gb + (w - 4) * NDIM + n0) = t0;
            *(ulonglong2*)(s_gb + (w - 4) * NDIM + n1) = t1;
        }
        __syncthreads();
        if (w < 4) {
            ulonglong2 t0 = *(ulonglong2*)(s_gb + w * NDIM + n0);
            ulonglong2 t1 = *(ulonglong2*)(s_gb + w * NDIM + n1);
            t0.x = add2(ga0, t0.x); t0.y = add2(ga1, t0.y);
            t1.x = add2(ga2, t1.x); t1.y = add2(ga3, t1.y);
            *(ulonglong2*)(s_gb + w * NDIM + n0) = t0;
            *(ulonglong2*)(s_gb + w * NDIM + n1) = t1;
        }
        __syncthreads();

        // grad + column-constraint mask bits (per-thread, serial + fast path)
        if (tid < NDIM) {
            float gb = 0.f;
#pragma unroll
            for (int j = 0; j < 4; j++) gb += s_gb[j * NDIM + tid];
            const float xv  = s_x[tid];
            const float lov = s_lo[tid];
            const float slo = fmaxf(xv - lov, 1e-12f);
            const float gr  = (xv - s_xr[tid]) + gb + __fdividef(MUF, slo);
            s_grad[tid] = gr;

            const float lim = lov + EPSF;
            if (!(gr <= 0.f && xv >= lim)) {   // fast path: all candidates pass
                unsigned mk = MASK_ALL;
                float st = 1.f;
#pragma unroll
                for (int l = 0; l < LMAX; l++) {
                    const float c = fmaf(-st, gr, xv);
                    if (!(c >= lim)) mk &= ~(1u << l);
                    st *= 0.5f;
                }
                if (mk != MASK_ALL) atomicAnd(&s_mask, mk);
            }
        }
        __syncthreads();

        // ---- pass A: raw Ag dots (8-row batched butterfly), scaled by inorm,
        //      + ballot row masks -------------------------------------------
        const ulonglong2 gA = *(const ulonglong2*)(s_grad + n0);
        const ulonglong2 gB = *(const ulonglong2*)(s_grad + n1);
        unsigned wmask = MASK_ALL;
        const int rrow = ((lane >> 4) & 1) * 4 + ((lane >> 3) & 1) * 2
                       + ((lane >> 2) & 1);   // row index this lane's sum maps to

#define PA_DOT(A0, A1, dst)                                                   \
        do {                                                                  \
            u64 s_ = mul2((A0).x, gA.x);                                      \
            s_ = fma2((A0).y, gA.y, s_);                                      \
            s_ = fma2((A1).x, gB.x, s_);                                      \
            s_ = fma2((A1).y, gB.y, s_);                                      \
            float sl_, sh_; unpack2(s_, sl_, sh_);                            \
            dst = sl_ + sh_;                                                  \
        } while (0)

        {
            // batch 1: rows j = 8..15 (gmem, raw)
            float prt[8];
#pragma unroll
            for (int i = 0; i < 8; i++) {
                const int m = w + 8 * (8 + i);
                const ulonglong2 a0 = *(const ulonglong2*)(A + (size_t)m * NDIM + n0);
                const ulonglong2 a1 = *(const ulonglong2*)(A + (size_t)m * NDIM + n1);
                PA_DOT(a0, a1, prt[i]);
            }
            float S = mreduce8(prt, lane);
            const int mlane = w + 8 * (8 + rrow);
            S *= s_in[mlane];                    // fold 1/norm into Ag
            if ((lane & 3) == 0) s_Ag[mlane] = S;
#pragma unroll
            for (int i = 0; i < 8; i++) {
                const float ag = __shfl_sync(0xffffffffu, S, 4 * i);
                const int m = w + 8 * (8 + i);
                const float axc = fmaf(-stepl, ag, s_Ax[m]);
                const unsigned bits =
                    __ballot_sync(0xffffffffu, axc <= s_bw[m] - EPSF);
                wmask &= (bits | ~MASK_ALL);
            }
        }
        {
            // batch 2: rows j = 0..7 (pinned i<5; i==5 pinned iff w<4; else gmem)
            float prt[8];
#pragma unroll
            for (int i = 0; i < 8; i++) {
                const int m = w + 8 * i;
                const float* src =
                    (i < CJ) ? (sA + m * NDIM)
                  : ((i == 5) ? ((w < 4) ? (sA + m * NDIM)
                                         : (A + (size_t)m * NDIM))
                              : (A + (size_t)m * NDIM));
                const ulonglong2 a0 = *(const ulonglong2*)(src + n0);
                const ulonglong2 a1 = *(const ulonglong2*)(src + n1);
                PA_DOT(a0, a1, prt[i]);
            }
            float S = mreduce8(prt, lane);
            const int mlane = w + 8 * rrow;
            S *= s_in[mlane];                    // fold 1/norm into Ag
            if ((lane & 3) == 0) s_Ag[mlane] = S;
#pragma unroll
            for (int i = 0; i < 8; i++) {
                const float ag = __shfl_sync(0xffffffffu, S, 4 * i);
                const int m = w + 8 * i;
                const float axc = fmaf(-stepl, ag, s_Ax[m]);
                const unsigned bits =
                    __ballot_sync(0xffffffffu, axc <= s_bw[m] - EPSF);
                wmask &= (bits | ~MASK_ALL);
            }
        }
#undef PA_DOT

        if (lane == 0 && wmask != MASK_ALL) atomicAnd(&s_mask, wmask);

        // cross-barrier prefetch for NEXT iteration's pass G (row j = 6):
        // A is constant -> no dependency; L2 latency hides under the spin.
        pf0 = *(const ulonglong2*)(A + (size_t)(w + 48) * NDIM + n0);
        pf1 = *(const ulonglong2*)(A + (size_t)(w + 48) * NDIM + n1);

        __syncthreads();

        // ---- flat global barrier; release word carries the step -------------
        if (tid == 0) {
            atomicAnd(&g_and[k], s_mask);
            __threadfence();
            if (atomicAdd(&g_cnt[k], 1u) == NPROB - 1u) {   // last arrival
                __threadfence();
                const unsigned fin = *(volatile unsigned*)&g_and[k] & MASK_ALL;
                const unsigned sb = fin ? (unsigned)(__ffs(fin) - 1) : 0xFFu;
                atomicExch(&g_rel, ((unsigned)(k + 1) << 8) | sb);
            }
            unsigned relv;
            while (((relv = *(volatile unsigned*)&g_rel) >> 8) != (unsigned)(k + 1))
                __nanosleep(32);
            const unsigned sb = relv & 0xFFu;
            s_step = (sb == 0xFFu) ? 0.f
                                   : __uint_as_float((127u - sb) << 23);
            s_mask = MASK_ALL;                // reset for next iteration
        }
        __syncthreads();

        // EXACT early exit: step==0 leaves x unchanged, so every remaining
        // iteration recomputes identical masks and also accepts nothing.
        // The decision is uniform across all CTAs (same release word).
        if (s_step == 0.f) break;

        // owner-thread updates: x, Ax, and v' for the next iteration
        if (tid < NDIM) s_x[tid] = fmaf(-s_step, s_grad[tid], s_x[tid]);
        if (tid < MDIM) {
            const float nAx = fmaf(-s_step, s_Ag[tid], s_Ax[tid]);
            s_Ax[tid] = nAx;
            s_v[tid]  = __fdividef(MUF, fmaxf(s_bw[tid] - nAx, 1e-12f)) * s_in[tid];
        }
        __syncthreads();   // s_v/s_x/s_mask visible to all for next iteration
    }

    // finalize: relu(x) -> out
    if (tid < NDIM) out[p * NDIM + tid] = fmaxf(s_x[tid], 0.f);
}

extern "C" void kernel_launch(void* const* d_in, const int* in_sizes, int n_in,
                              void* d_out, int out_size) {
    // Identify inputs by size (dict order: x_raw, A, b, lower).
    int iA = 1, ib = 2, iv1 = 0, iv2 = 3;
    {
        int big = -1, small = -1, v1 = -1, v2 = -1;
        for (int i = 0; i < n_in; i++) {
            if (in_sizes[i] == NPROB * MDIM * NDIM) big = i;
            else if (in_sizes[i] == NPROB * MDIM)   small = i;
            else if (v1 < 0) v1 = i;
            else             v2 = i;
        }
        if (big >= 0 && small >= 0 && v1 >= 0 && v2 >= 0) {
            iA = big; ib = small; iv1 = v1; iv2 = v2;
        }
    }
    const float* xr  = (const float*)d_in[iv1];
    const float* A   = (const float*)d_in[iA];
    const float* b   = (const float*)d_in[ib];
    const float* low = (const float*)d_in[iv2];
    float* out = (float*)d_out;

    // Opt-in: static (~10.8KB) + dynamic (44KB) > 48KB default per-block limit.
    // Not a stream-ordered call -> does not enter / invalidate graph capture.
    cudaFuncSetAttribute(persist_kernel,
                         cudaFuncAttributeMaxDynamicSharedMemorySize, DYNSMEM);

    persist_kernel<<<NPROB, TPB, DYNSMEM>>>(xr, A, b, low, out);
}